// round 1
// baseline (speedup 1.0000x reference)
#include <cuda_runtime.h>
#include <math.h>

// Problem constants (fixed by setup_inputs)
#define D_MODEL 1024
#define N_HEAD  16
#define D_H     64
#define BATCH   4
#define LQ      1024
#define LK      2048

// Attention tiling
#define QT 64   // query rows per block
#define KT 32   // key rows per tile

// ---------------------------------------------------------------------------
// Scratch (no cudaMalloc allowed): q/k/v projections + attention output
// ---------------------------------------------------------------------------
__device__ float g_q   [(size_t)BATCH * LQ * D_MODEL];
__device__ float g_k   [(size_t)BATCH * LK * D_MODEL];
__device__ float g_v   [(size_t)BATCH * LK * D_MODEL];
__device__ float g_attn[(size_t)BATCH * LQ * D_MODEL];

// ---------------------------------------------------------------------------
// SGEMM: C[M,N] = A[M,K] @ W[K,N] + bias[N]   (all row-major, fp32)
// 128x128 block tile, BK=8, 256 threads, 8x8 microtile per thread.
// Requires M%128==0, N%128==0, K%8==0 (true for all calls here).
// ---------------------------------------------------------------------------
__global__ __launch_bounds__(256) void gemm_bias_kernel(
    const float* __restrict__ A, const float* __restrict__ W,
    const float* __restrict__ bias, float* __restrict__ C,
    int M, int N, int K)
{
    __shared__ float As[8][128];   // transposed A tile: As[k][m]
    __shared__ float Bs[8][128];   // Bs[k][n]

    const int tid  = threadIdx.x;
    const int tx   = tid & 15;     // 0..15 -> 8 output cols each
    const int ty   = tid >> 4;     // 0..15 -> 8 output rows each
    const int brow = blockIdx.y * 128;
    const int bcol = blockIdx.x * 128;

    const int a_row = tid >> 1;          // 0..127
    const int a_col = (tid & 1) * 4;     // 0 or 4
    const int b_row = tid >> 5;          // 0..7
    const int b_col = (tid & 31) * 4;    // 0..124

    float acc[8][8];
#pragma unroll
    for (int i = 0; i < 8; i++)
#pragma unroll
        for (int j = 0; j < 8; j++) acc[i][j] = 0.0f;

    for (int k0 = 0; k0 < K; k0 += 8) {
        float4 av = *reinterpret_cast<const float4*>(
            A + (size_t)(brow + a_row) * K + k0 + a_col);
        As[a_col + 0][a_row] = av.x;
        As[a_col + 1][a_row] = av.y;
        As[a_col + 2][a_row] = av.z;
        As[a_col + 3][a_row] = av.w;
        *reinterpret_cast<float4*>(&Bs[b_row][b_col]) =
            *reinterpret_cast<const float4*>(
                W + (size_t)(k0 + b_row) * N + bcol + b_col);
        __syncthreads();

#pragma unroll
        for (int k = 0; k < 8; k++) {
            float ar[8], br[8];
#pragma unroll
            for (int i = 0; i < 8; i++) ar[i] = As[k][ty * 8 + i];
#pragma unroll
            for (int j = 0; j < 8; j++) br[j] = Bs[k][tx * 8 + j];
#pragma unroll
            for (int i = 0; i < 8; i++)
#pragma unroll
                for (int j = 0; j < 8; j++)
                    acc[i][j] = fmaf(ar[i], br[j], acc[i][j]);
        }
        __syncthreads();
    }

#pragma unroll
    for (int i = 0; i < 8; i++) {
        const int row = brow + ty * 8 + i;
#pragma unroll
        for (int j = 0; j < 8; j += 4) {
            const int col = bcol + tx * 8 + j;
            float4 o;
            o.x = acc[i][j + 0] + bias[col + 0];
            o.y = acc[i][j + 1] + bias[col + 1];
            o.z = acc[i][j + 2] + bias[col + 2];
            o.w = acc[i][j + 3] + bias[col + 3];
            *reinterpret_cast<float4*>(C + (size_t)row * N + col) = o;
        }
    }
}

// ---------------------------------------------------------------------------
// Flash attention (fp32, online softmax).
// Grid: (LQ/QT, N_HEAD, BATCH), 128 threads.
// Thread t owns query row r = t/2; p = t&1 selects half of the K-cols
// (S phase) / half of the D_H output cols (O phase). Pair reduces via shfl.
// ---------------------------------------------------------------------------
__global__ __launch_bounds__(128) void attn_kernel(const int* __restrict__ mask)
{
    __shared__ float Qs[QT * D_H];     // pre-scaled by 1/sqrt(dh)
    __shared__ float Ks[KT * D_H];
    __shared__ float Vs[KT * D_H];
    __shared__ float Ps[QT * KT];
    __shared__ float m_s[QT], l_s[QT], corr_s[QT];
    __shared__ float bias_s[KT];

    const int tid = threadIdx.x;
    const int q0  = blockIdx.x * QT;
    const int h   = blockIdx.y;
    const int b   = blockIdx.z;

    const float* qbase = g_q + (size_t)b * LQ * D_MODEL + (size_t)h * D_H;
    const float* kbase = g_k + (size_t)b * LK * D_MODEL + (size_t)h * D_H;
    const float* vbase = g_v + (size_t)b * LK * D_MODEL + (size_t)h * D_H;

    const float scale = 0.125f;  // 1/sqrt(64)
    // Q tile: QT rows x 16 float4
    for (int i = tid; i < QT * 16; i += 128) {
        const int r  = i >> 4;
        const int c4 = (i & 15) * 4;
        float4 v = *reinterpret_cast<const float4*>(
            qbase + (size_t)(q0 + r) * D_MODEL + c4);
        Qs[r * D_H + c4 + 0] = v.x * scale;
        Qs[r * D_H + c4 + 1] = v.y * scale;
        Qs[r * D_H + c4 + 2] = v.z * scale;
        Qs[r * D_H + c4 + 3] = v.w * scale;
    }
    if (tid < QT) { m_s[tid] = -3.0e38f; l_s[tid] = 0.0f; }

    const int r = tid >> 1;
    const int p = tid & 1;
    float o[32];
#pragma unroll
    for (int d = 0; d < 32; d++) o[d] = 0.0f;

    for (int kt = 0; kt < LK; kt += KT) {
        __syncthreads();  // protect Ks/Vs/Ps from previous iteration; Q/stat init on first
        for (int i = tid; i < KT * 16; i += 128) {
            const int rr = i >> 4;
            const int c4 = (i & 15) * 4;
            *reinterpret_cast<float4*>(&Ks[rr * D_H + c4]) =
                *reinterpret_cast<const float4*>(kbase + (size_t)(kt + rr) * D_MODEL + c4);
            *reinterpret_cast<float4*>(&Vs[rr * D_H + c4]) =
                *reinterpret_cast<const float4*>(vbase + (size_t)(kt + rr) * D_MODEL + c4);
        }
        if (tid < KT)
            bias_s[tid] = mask[(size_t)b * LK + kt + tid] ? -1.0e30f : 0.0f;
        __syncthreads();

        // ---- S = Q K^T (row r, 16 cols starting at p*16) ----
        float s[16];
#pragma unroll
        for (int j = 0; j < 16; j++) {
            const int kk = p * 16 + j;
            float a = 0.0f;
#pragma unroll
            for (int d = 0; d < D_H; d++)
                a = fmaf(Qs[r * D_H + d], Ks[kk * D_H + d], a);
            s[j] = a + bias_s[kk];
        }
        float mx = s[0];
#pragma unroll
        for (int j = 1; j < 16; j++) mx = fmaxf(mx, s[j]);
        mx = fmaxf(mx, __shfl_xor_sync(0xffffffffu, mx, 1));

        const float m_old = m_s[r];
        const float m_new = fmaxf(m_old, mx);
        float psum = 0.0f;
#pragma unroll
        for (int j = 0; j < 16; j++) {
            const float pv = __expf(s[j] - m_new);
            Ps[r * KT + p * 16 + j] = pv;
            psum += pv;
        }
        psum += __shfl_xor_sync(0xffffffffu, psum, 1);
        if (p == 0) {
            const float corr = __expf(m_old - m_new);
            corr_s[r] = corr;
            m_s[r]    = m_new;
            l_s[r]    = l_s[r] * corr + psum;
        }
        __syncthreads();

        // ---- O = O*corr + P V (row r, 32 d-cols starting at p*32) ----
        const float corr = corr_s[r];
#pragma unroll
        for (int d = 0; d < 32; d++) o[d] *= corr;
        for (int kk = 0; kk < KT; kk++) {
            const float pv = Ps[r * KT + kk];
#pragma unroll
            for (int d = 0; d < 32; d++)
                o[d] = fmaf(pv, Vs[kk * D_H + p * 32 + d], o[d]);
        }
    }

    const float linv = 1.0f / l_s[r];
    float* obase = g_attn + (size_t)(b * LQ + q0 + r) * D_MODEL
                 + (size_t)h * D_H + p * 32;
#pragma unroll
    for (int d = 0; d < 32; d++) obase[d] = o[d] * linv;
}

// ---------------------------------------------------------------------------
// Launch
// ---------------------------------------------------------------------------
extern "C" void kernel_launch(void* const* d_in, const int* in_sizes, int n_in,
                              void* d_out, int out_size)
{
    const float* q_in  = (const float*)d_in[0];
    const float* kv_in = (const float*)d_in[1];
    const int*   mask  = (const int*)  d_in[2];
    const float* W_Q   = (const float*)d_in[3];
    const float* b_Q   = (const float*)d_in[4];
    const float* W_K   = (const float*)d_in[5];
    const float* b_K   = (const float*)d_in[6];
    const float* W_V   = (const float*)d_in[7];
    const float* b_V   = (const float*)d_in[8];
    const float* W_O   = (const float*)d_in[9];
    const float* b_O   = (const float*)d_in[10];

    float *q_p, *k_p, *v_p, *a_p;
    cudaGetSymbolAddress((void**)&q_p, g_q);
    cudaGetSymbolAddress((void**)&k_p, g_k);
    cudaGetSymbolAddress((void**)&v_p, g_v);
    cudaGetSymbolAddress((void**)&a_p, g_attn);

    const dim3 thr(256);
    const dim3 gq(D_MODEL / 128, (BATCH * LQ) / 128);
    const dim3 gk(D_MODEL / 128, (BATCH * LK) / 128);

    gemm_bias_kernel<<<gq, thr>>>(q_in,  W_Q, b_Q, q_p, BATCH * LQ, D_MODEL, D_MODEL);
    gemm_bias_kernel<<<gk, thr>>>(kv_in, W_K, b_K, k_p, BATCH * LK, D_MODEL, D_MODEL);
    gemm_bias_kernel<<<gk, thr>>>(kv_in, W_V, b_V, v_p, BATCH * LK, D_MODEL, D_MODEL);

    const dim3 ga(LQ / QT, N_HEAD, BATCH);
    attn_kernel<<<ga, 128>>>(mask);

    gemm_bias_kernel<<<gq, thr>>>(a_p, W_O, b_O, (float*)d_out,
                                  BATCH * LQ, D_MODEL, D_MODEL);
}

// round 3
// speedup vs baseline: 1.9466x; 1.9466x over previous
#include <cuda_runtime.h>
#include <cuda_bf16.h>
#include <stdint.h>
#include <math.h>

#define D_MODEL 1024
#define N_HEAD  16
#define D_H     64
#define BATCH   4
#define LQ      1024
#define LK      2048

// ---------------------------------------------------------------------------
// Scratch (no cudaMalloc allowed)
// ---------------------------------------------------------------------------
__device__ float g_q   [(size_t)BATCH * LQ * D_MODEL];
__device__ float g_k   [(size_t)BATCH * LK * D_MODEL];
__device__ float g_v   [(size_t)BATCH * LK * D_MODEL];
__device__ float g_attn[(size_t)BATCH * LQ * D_MODEL];

// ---------------------------------------------------------------------------
// Helpers
// ---------------------------------------------------------------------------
__device__ __forceinline__ uint32_t smem_u32(const void* p) {
    uint32_t a;
    asm("{ .reg .u64 t; cvta.to.shared.u64 t, %1; cvt.u32.u64 %0, t; }"
        : "=r"(a) : "l"(p));
    return a;
}

__device__ __forceinline__ void ldm_x4(uint32_t* r, uint32_t addr) {
    asm volatile("ldmatrix.sync.aligned.m8n8.x4.shared.b16 {%0,%1,%2,%3}, [%4];"
                 : "=r"(r[0]), "=r"(r[1]), "=r"(r[2]), "=r"(r[3]) : "r"(addr));
}
__device__ __forceinline__ void ldm_x2_trans(uint32_t* r, uint32_t addr) {
    asm volatile("ldmatrix.sync.aligned.m8n8.x2.trans.shared.b16 {%0,%1}, [%2];"
                 : "=r"(r[0]), "=r"(r[1]) : "r"(addr));
}
__device__ __forceinline__ void mma_bf16(float* c, const uint32_t* a, const uint32_t* b) {
    asm volatile(
        "mma.sync.aligned.m16n8k16.row.col.f32.bf16.bf16.f32 "
        "{%0,%1,%2,%3}, {%4,%5,%6,%7}, {%8,%9}, {%0,%1,%2,%3};"
        : "+f"(c[0]), "+f"(c[1]), "+f"(c[2]), "+f"(c[3])
        : "r"(a[0]), "r"(a[1]), "r"(a[2]), "r"(a[3]), "r"(b[0]), "r"(b[1]));
}

// ---------------------------------------------------------------------------
// bf16-split tensor-core GEMM: C[M,N] = A[M,K] @ W[K,N] + bias (fp32 in/out).
// 128x128 block tile, BK=32, 256 threads (8 warps), warp tile 64x32.
// 3 MMA passes: Ah*Bh + Ah*Bl + Al*Bh  (Al*Bl term ~2^-18, dropped).
// ---------------------------------------------------------------------------
#define APAD 40    // row stride (bf16) for A tiles: 80B = 5*16B -> conflict-free
#define BPAD 136   // row stride (bf16) for B tiles: 272B = 17*16B -> conflict-free

__global__ __launch_bounds__(256) void gemm_mma(
    const float* __restrict__ A, const float* __restrict__ W,
    const float* __restrict__ bias, float* __restrict__ C,
    int M, int K, int N)
{
    __shared__ __align__(16) __nv_bfloat16 Ah[128 * APAD];
    __shared__ __align__(16) __nv_bfloat16 Al[128 * APAD];
    __shared__ __align__(16) __nv_bfloat16 Bh[32 * BPAD];
    __shared__ __align__(16) __nv_bfloat16 Bl[32 * BPAD];

    const int tid  = threadIdx.x;
    const int warp = tid >> 5, lane = tid & 31;
    const int wm   = warp >> 2;        // 0..1  -> m offset wm*64
    const int wn   = warp & 3;         // 0..3  -> n offset wn*32
    const int brow = blockIdx.y * 128;
    const int bcol = blockIdx.x * 128;

    float acc[4][4][4];
#pragma unroll
    for (int mi = 0; mi < 4; mi++)
#pragma unroll
        for (int ni = 0; ni < 4; ni++)
#pragma unroll
            for (int r = 0; r < 4; r++) acc[mi][ni][r] = 0.0f;

    const uint32_t ah_b = smem_u32(Ah), al_b = smem_u32(Al);
    const uint32_t bh_b = smem_u32(Bh), bl_b = smem_u32(Bl);

    for (int k0 = 0; k0 < K; k0 += 32) {
        // ---- load A tile: 128 x 32 fp32, split into bf16 hi/lo ----
#pragma unroll
        for (int it = 0; it < 8; ++it) {
            const int idx = it * 256 + tid;
            const int m = idx >> 4, kp = idx & 15;   // kp: float2 index
            float2 a2 = *reinterpret_cast<const float2*>(
                A + (size_t)(brow + m) * K + k0 + 2 * kp);
            __nv_bfloat162 h2 = __float22bfloat162_rn(a2);
            float2 hf = __bfloat1622float2(h2);
            __nv_bfloat162 l2 = __float22bfloat162_rn(
                make_float2(a2.x - hf.x, a2.y - hf.y));
            const int off = m * APAD + 2 * kp;
            *reinterpret_cast<uint32_t*>(&Ah[off]) = *reinterpret_cast<uint32_t*>(&h2);
            *reinterpret_cast<uint32_t*>(&Al[off]) = *reinterpret_cast<uint32_t*>(&l2);
        }
        // ---- load B tile: 32 x 128 fp32 (direct rows of W), hi/lo ----
#pragma unroll
        for (int it = 0; it < 4; ++it) {
            const int idx = it * 256 + tid;
            const int k = idx >> 5, n4 = (idx & 31) * 4;
            float4 w4 = *reinterpret_cast<const float4*>(
                W + (size_t)(k0 + k) * N + bcol + n4);
            __nv_bfloat162 h0 = __float22bfloat162_rn(make_float2(w4.x, w4.y));
            __nv_bfloat162 h1 = __float22bfloat162_rn(make_float2(w4.z, w4.w));
            float2 f0 = __bfloat1622float2(h0);
            float2 f1 = __bfloat1622float2(h1);
            __nv_bfloat162 l0 = __float22bfloat162_rn(make_float2(w4.x - f0.x, w4.y - f0.y));
            __nv_bfloat162 l1 = __float22bfloat162_rn(make_float2(w4.z - f1.x, w4.w - f1.y));
            const int off = k * BPAD + n4;
            *reinterpret_cast<uint32_t*>(&Bh[off])     = *reinterpret_cast<uint32_t*>(&h0);
            *reinterpret_cast<uint32_t*>(&Bh[off + 2]) = *reinterpret_cast<uint32_t*>(&h1);
            *reinterpret_cast<uint32_t*>(&Bl[off])     = *reinterpret_cast<uint32_t*>(&l0);
            *reinterpret_cast<uint32_t*>(&Bl[off + 2]) = *reinterpret_cast<uint32_t*>(&l1);
        }
        __syncthreads();

        // ---- 3 passes x 2 k-steps of m16n8k16 ----
#pragma unroll
        for (int p = 0; p < 3; p++) {
            const uint32_t ab = (p == 2) ? al_b : ah_b;
            const uint32_t bb = (p == 1) ? bl_b : bh_b;
#pragma unroll
            for (int ks = 0; ks < 2; ks++) {
                uint32_t af[4][4], bf[4][2];
#pragma unroll
                for (int mi = 0; mi < 4; mi++) {
                    const int row = wm * 64 + mi * 16 + (lane & 15);
                    const int col = ks * 16 + (lane >> 4) * 8;
                    ldm_x4(af[mi], ab + (uint32_t)(row * APAD + col) * 2);
                }
#pragma unroll
                for (int ni = 0; ni < 4; ni++) {
                    const int krow = ks * 16 + (lane & 15);
                    const int ncol = wn * 32 + ni * 8;
                    ldm_x2_trans(bf[ni], bb + (uint32_t)(krow * BPAD + ncol) * 2);
                }
#pragma unroll
                for (int mi = 0; mi < 4; mi++)
#pragma unroll
                    for (int ni = 0; ni < 4; ni++)
                        mma_bf16(acc[mi][ni], af[mi], bf[ni]);
            }
        }
        __syncthreads();
    }

    // ---- epilogue: fragments -> global + bias ----
    const int g = lane >> 2, t4 = lane & 3;
#pragma unroll
    for (int mi = 0; mi < 4; mi++) {
        const int row = brow + wm * 64 + mi * 16 + g;
#pragma unroll
        for (int ni = 0; ni < 4; ni++) {
            const int col = bcol + wn * 32 + ni * 8 + 2 * t4;
            const float b0 = bias[col], b1 = bias[col + 1];
            float2 v0 = make_float2(acc[mi][ni][0] + b0, acc[mi][ni][1] + b1);
            float2 v1 = make_float2(acc[mi][ni][2] + b0, acc[mi][ni][3] + b1);
            *reinterpret_cast<float2*>(C + (size_t)row * N + col)       = v0;
            *reinterpret_cast<float2*>(C + (size_t)(row + 8) * N + col) = v1;
        }
    }
}

// ---------------------------------------------------------------------------
// Register-tiled flash attention (fp32).
// Grid (LQ/64, N_HEAD, BATCH), 128 threads.
// ---------------------------------------------------------------------------
#define QT 64
#define KT 32

__global__ __launch_bounds__(128) void attn_kernel(const int* __restrict__ mask)
{
    __shared__ float Qs[QT * 65];
    __shared__ float Ks[KT * 65];
    __shared__ __align__(16) float Vs[KT * 64];
    __shared__ float Ps[QT * 33];
    __shared__ float m_s[QT], l_s[QT], corr_s[QT];
    __shared__ float bias_s[KT];

    const int tid = threadIdx.x;
    const int q0  = blockIdx.x * QT;
    const int h   = blockIdx.y;
    const int b   = blockIdx.z;

    const float* qbase = g_q + (size_t)b * LQ * D_MODEL + (size_t)h * D_H;
    const float* kbase = g_k + (size_t)b * LK * D_MODEL + (size_t)h * D_H;
    const float* vbase = g_v + (size_t)b * LK * D_MODEL + (size_t)h * D_H;

    const float scale = 0.125f;  // 1/sqrt(64)
    for (int i = tid; i < QT * D_H; i += 128) {
        const int r = i >> 6, d = i & 63;
        Qs[r * 65 + d] = qbase[(size_t)(q0 + r) * D_MODEL + d] * scale;
    }
    if (tid < QT) { m_s[tid] = -3.0e38f; l_s[tid] = 0.0f; }

    const int ig = tid >> 3;       // 0..15 -> rows 4ig..4ig+3
    const int jg = tid & 7;        // 0..7  -> S cols 4jg..+3, O d-cols 8jg..+7
    const int r0 = ig * 4;
    const int c0 = jg * 4;
    const int d0 = jg * 8;

    float o[4][8];
#pragma unroll
    for (int i = 0; i < 4; i++)
#pragma unroll
        for (int j = 0; j < 8; j++) o[i][j] = 0.0f;

    for (int kt = 0; kt < LK; kt += KT) {
        __syncthreads();
        for (int i = tid; i < KT * D_H; i += 128) {
            const int c = i >> 6, d = i & 63;
            Ks[c * 65 + d] = kbase[(size_t)(kt + c) * D_MODEL + d];
        }
        for (int i = tid; i < KT * 16; i += 128) {
            const int kk = i >> 4, d4 = (i & 15) * 4;
            *reinterpret_cast<float4*>(&Vs[kk * 64 + d4]) =
                *reinterpret_cast<const float4*>(vbase + (size_t)(kt + kk) * D_MODEL + d4);
        }
        if (tid < KT)
            bias_s[tid] = mask[(size_t)b * LK + kt + tid] ? -1.0e30f : 0.0f;
        __syncthreads();

        // ---- S = Q K^T : 4x4 register tile ----
        float acc[4][4];
#pragma unroll
        for (int i = 0; i < 4; i++)
#pragma unroll
            for (int j = 0; j < 4; j++) acc[i][j] = 0.0f;

#pragma unroll 4
        for (int d = 0; d < D_H; d++) {
            float qr[4], kr[4];
#pragma unroll
            for (int i = 0; i < 4; i++) qr[i] = Qs[(r0 + i) * 65 + d];
#pragma unroll
            for (int j = 0; j < 4; j++) kr[j] = Ks[(c0 + j) * 65 + d];
#pragma unroll
            for (int i = 0; i < 4; i++)
#pragma unroll
                for (int j = 0; j < 4; j++)
                    acc[i][j] = fmaf(qr[i], kr[j], acc[i][j]);
        }
#pragma unroll
        for (int j = 0; j < 4; j++) {
            const float bj = bias_s[c0 + j];
#pragma unroll
            for (int i = 0; i < 4; i++) acc[i][j] += bj;
        }

        float mx[4];
#pragma unroll
        for (int i = 0; i < 4; i++) {
            float m = fmaxf(fmaxf(acc[i][0], acc[i][1]), fmaxf(acc[i][2], acc[i][3]));
            m = fmaxf(m, __shfl_xor_sync(0xffffffffu, m, 1));
            m = fmaxf(m, __shfl_xor_sync(0xffffffffu, m, 2));
            m = fmaxf(m, __shfl_xor_sync(0xffffffffu, m, 4));
            mx[i] = m;
        }

        float m_old[4], m_new[4], psum[4];
#pragma unroll
        for (int i = 0; i < 4; i++) {
            m_old[i] = m_s[r0 + i];
            m_new[i] = fmaxf(m_old[i], mx[i]);
            float ps = 0.0f;
#pragma unroll
            for (int j = 0; j < 4; j++) {
                const float p = __expf(acc[i][j] - m_new[i]);
                Ps[(r0 + i) * 33 + c0 + j] = p;
                ps += p;
            }
            ps += __shfl_xor_sync(0xffffffffu, ps, 1);
            ps += __shfl_xor_sync(0xffffffffu, ps, 2);
            ps += __shfl_xor_sync(0xffffffffu, ps, 4);
            psum[i] = ps;
        }
        if (jg == 0) {
#pragma unroll
            for (int i = 0; i < 4; i++) {
                const float corr = __expf(m_old[i] - m_new[i]);
                corr_s[r0 + i] = corr;
                m_s[r0 + i]    = m_new[i];
                l_s[r0 + i]    = l_s[r0 + i] * corr + psum[i];
            }
        }
        __syncthreads();

        // ---- O = O*corr + P V : 4x8 register tile ----
#pragma unroll
        for (int i = 0; i < 4; i++) {
            const float corr = corr_s[r0 + i];
#pragma unroll
            for (int j = 0; j < 8; j++) o[i][j] *= corr;
        }
#pragma unroll 2
        for (int kk = 0; kk < KT; kk++) {
            float pr[4];
#pragma unroll
            for (int i = 0; i < 4; i++) pr[i] = Ps[(r0 + i) * 33 + kk];
            const float4 va = *reinterpret_cast<const float4*>(&Vs[kk * 64 + d0]);
            const float4 vb = *reinterpret_cast<const float4*>(&Vs[kk * 64 + d0 + 4]);
#pragma unroll
            for (int i = 0; i < 4; i++) {
                o[i][0] = fmaf(pr[i], va.x, o[i][0]);
                o[i][1] = fmaf(pr[i], va.y, o[i][1]);
                o[i][2] = fmaf(pr[i], va.z, o[i][2]);
                o[i][3] = fmaf(pr[i], va.w, o[i][3]);
                o[i][4] = fmaf(pr[i], vb.x, o[i][4]);
                o[i][5] = fmaf(pr[i], vb.y, o[i][5]);
                o[i][6] = fmaf(pr[i], vb.z, o[i][6]);
                o[i][7] = fmaf(pr[i], vb.w, o[i][7]);
            }
        }
    }

#pragma unroll
    for (int i = 0; i < 4; i++) {
        const float linv = 1.0f / l_s[r0 + i];
        float* op = g_attn + (size_t)(b * LQ + q0 + r0 + i) * D_MODEL
                  + (size_t)h * D_H + d0;
        float4 oa = make_float4(o[i][0] * linv, o[i][1] * linv,
                                o[i][2] * linv, o[i][3] * linv);
        float4 ob = make_float4(o[i][4] * linv, o[i][5] * linv,
                                o[i][6] * linv, o[i][7] * linv);
        *reinterpret_cast<float4*>(op)     = oa;
        *reinterpret_cast<float4*>(op + 4) = ob;
    }
}

// ---------------------------------------------------------------------------
// Launch
// ---------------------------------------------------------------------------
extern "C" void kernel_launch(void* const* d_in, const int* in_sizes, int n_in,
                              void* d_out, int out_size)
{
    const float* q_in  = (const float*)d_in[0];
    const float* kv_in = (const float*)d_in[1];
    const int*   mask  = (const int*)  d_in[2];
    const float* W_Q   = (const float*)d_in[3];
    const float* b_Q   = (const float*)d_in[4];
    const float* W_K   = (const float*)d_in[5];
    const float* b_K   = (const float*)d_in[6];
    const float* W_V   = (const float*)d_in[7];
    const float* b_V   = (const float*)d_in[8];
    const float* W_O   = (const float*)d_in[9];
    const float* b_O   = (const float*)d_in[10];

    float *q_p, *k_p, *v_p, *a_p;
    cudaGetSymbolAddress((void**)&q_p, g_q);
    cudaGetSymbolAddress((void**)&k_p, g_k);
    cudaGetSymbolAddress((void**)&v_p, g_v);
    cudaGetSymbolAddress((void**)&a_p, g_attn);

    const dim3 thr(256);
    const dim3 gq(D_MODEL / 128, (BATCH * LQ) / 128);
    const dim3 gk(D_MODEL / 128, (BATCH * LK) / 128);

    gemm_mma<<<gq, thr>>>(q_in,  W_Q, b_Q, q_p, BATCH * LQ, D_MODEL, D_MODEL);
    gemm_mma<<<gk, thr>>>(kv_in, W_K, b_K, k_p, BATCH * LK, D_MODEL, D_MODEL);
    gemm_mma<<<gk, thr>>>(kv_in, W_V, b_V, v_p, BATCH * LK, D_MODEL, D_MODEL);

    const dim3 ga(LQ / QT, N_HEAD, BATCH);
    attn_kernel<<<ga, 128>>>(mask);

    gemm_mma<<<gq, thr>>>(a_p, W_O, b_O, (float*)d_out,
                          BATCH * LQ, D_MODEL, D_MODEL);
}

// round 4
// speedup vs baseline: 3.5504x; 1.8239x over previous
#include <cuda_runtime.h>
#include <cuda_bf16.h>
#include <stdint.h>
#include <math.h>

#define D_MODEL 1024
#define N_HEAD  16
#define D_H     64
#define BATCH   4
#define LQ      1024
#define LK      2048

// ---------------------------------------------------------------------------
// Scratch (no cudaMalloc allowed): split-bf16 projections + f32 attn output
// ---------------------------------------------------------------------------
__device__ __nv_bfloat16 g_qh[(size_t)BATCH * LQ * D_MODEL];
__device__ __nv_bfloat16 g_ql[(size_t)BATCH * LQ * D_MODEL];
__device__ __nv_bfloat16 g_kh[(size_t)BATCH * LK * D_MODEL];
__device__ __nv_bfloat16 g_kl[(size_t)BATCH * LK * D_MODEL];
__device__ __nv_bfloat16 g_vh[(size_t)BATCH * LK * D_MODEL];
__device__ __nv_bfloat16 g_vl[(size_t)BATCH * LK * D_MODEL];
__device__ float         g_attn[(size_t)BATCH * LQ * D_MODEL];

// ---------------------------------------------------------------------------
// Helpers
// ---------------------------------------------------------------------------
__device__ __forceinline__ uint32_t smem_u32(const void* p) {
    uint32_t a;
    asm("{ .reg .u64 t; cvta.to.shared.u64 t, %1; cvt.u32.u64 %0, t; }"
        : "=r"(a) : "l"(p));
    return a;
}
__device__ __forceinline__ void ldm_x4(uint32_t* r, uint32_t addr) {
    asm volatile("ldmatrix.sync.aligned.m8n8.x4.shared.b16 {%0,%1,%2,%3}, [%4];"
                 : "=r"(r[0]), "=r"(r[1]), "=r"(r[2]), "=r"(r[3]) : "r"(addr));
}
__device__ __forceinline__ void ldm_x2(uint32_t* r, uint32_t addr) {
    asm volatile("ldmatrix.sync.aligned.m8n8.x2.shared.b16 {%0,%1}, [%2];"
                 : "=r"(r[0]), "=r"(r[1]) : "r"(addr));
}
__device__ __forceinline__ void ldm_x2_trans(uint32_t* r, uint32_t addr) {
    asm volatile("ldmatrix.sync.aligned.m8n8.x2.trans.shared.b16 {%0,%1}, [%2];"
                 : "=r"(r[0]), "=r"(r[1]) : "r"(addr));
}
__device__ __forceinline__ void mma_bf16(float* c, const uint32_t* a, const uint32_t* b) {
    asm volatile(
        "mma.sync.aligned.m16n8k16.row.col.f32.bf16.bf16.f32 "
        "{%0,%1,%2,%3}, {%4,%5,%6,%7}, {%8,%9}, {%0,%1,%2,%3};"
        : "+f"(c[0]), "+f"(c[1]), "+f"(c[2]), "+f"(c[3])
        : "r"(a[0]), "r"(a[1]), "r"(a[2]), "r"(a[3]), "r"(b[0]), "r"(b[1]));
}
// split f32 pair -> bf16x2 hi + bf16x2 lo (packed u32)
__device__ __forceinline__ void split2(float a, float b, uint32_t& hi, uint32_t& lo) {
    __nv_bfloat162 h2 = __float22bfloat162_rn(make_float2(a, b));
    float2 hf = __bfloat1622float2(h2);
    __nv_bfloat162 l2 = __float22bfloat162_rn(make_float2(a - hf.x, b - hf.y));
    hi = *reinterpret_cast<uint32_t*>(&h2);
    lo = *reinterpret_cast<uint32_t*>(&l2);
}

// ---------------------------------------------------------------------------
// bf16-split tensor-core GEMM: 128x128 tile, BK=32, 256 thr, warp tile 64x32.
// MODE 0: C = A@W + bias (fp32 out).  MODE 1: split-bf16 out, (acc+bias)*scale.
// ---------------------------------------------------------------------------
#define APAD 40
#define BPAD 136

template <int MODE>
__global__ __launch_bounds__(256) void gemm_mma(
    const float* __restrict__ A, const float* __restrict__ W,
    const float* __restrict__ bias, float* __restrict__ C,
    __nv_bfloat16* __restrict__ Ch, __nv_bfloat16* __restrict__ Cl,
    float scale, int M, int K, int N)
{
    __shared__ __align__(16) __nv_bfloat16 Ah[128 * APAD];
    __shared__ __align__(16) __nv_bfloat16 Al[128 * APAD];
    __shared__ __align__(16) __nv_bfloat16 Bh[32 * BPAD];
    __shared__ __align__(16) __nv_bfloat16 Bl[32 * BPAD];

    const int tid  = threadIdx.x;
    const int warp = tid >> 5, lane = tid & 31;
    const int wm   = warp >> 2;
    const int wn   = warp & 3;
    const int brow = blockIdx.y * 128;
    const int bcol = blockIdx.x * 128;

    float acc[4][4][4];
#pragma unroll
    for (int mi = 0; mi < 4; mi++)
#pragma unroll
        for (int ni = 0; ni < 4; ni++)
#pragma unroll
            for (int r = 0; r < 4; r++) acc[mi][ni][r] = 0.0f;

    const uint32_t ah_b = smem_u32(Ah), al_b = smem_u32(Al);
    const uint32_t bh_b = smem_u32(Bh), bl_b = smem_u32(Bl);

    for (int k0 = 0; k0 < K; k0 += 32) {
#pragma unroll
        for (int it = 0; it < 8; ++it) {
            const int idx = it * 256 + tid;
            const int m = idx >> 4, kp = idx & 15;
            float2 a2 = *reinterpret_cast<const float2*>(
                A + (size_t)(brow + m) * K + k0 + 2 * kp);
            uint32_t h, l;
            split2(a2.x, a2.y, h, l);
            const int off = m * APAD + 2 * kp;
            *reinterpret_cast<uint32_t*>(&Ah[off]) = h;
            *reinterpret_cast<uint32_t*>(&Al[off]) = l;
        }
#pragma unroll
        for (int it = 0; it < 4; ++it) {
            const int idx = it * 256 + tid;
            const int k = idx >> 5, n4 = (idx & 31) * 4;
            float4 w4 = *reinterpret_cast<const float4*>(
                W + (size_t)(k0 + k) * N + bcol + n4);
            uint32_t h0, l0, h1, l1;
            split2(w4.x, w4.y, h0, l0);
            split2(w4.z, w4.w, h1, l1);
            const int off = k * BPAD + n4;
            *reinterpret_cast<uint32_t*>(&Bh[off])     = h0;
            *reinterpret_cast<uint32_t*>(&Bh[off + 2]) = h1;
            *reinterpret_cast<uint32_t*>(&Bl[off])     = l0;
            *reinterpret_cast<uint32_t*>(&Bl[off + 2]) = l1;
        }
        __syncthreads();

#pragma unroll
        for (int p = 0; p < 3; p++) {
            const uint32_t ab = (p == 2) ? al_b : ah_b;
            const uint32_t bb = (p == 1) ? bl_b : bh_b;
#pragma unroll
            for (int ks = 0; ks < 2; ks++) {
                uint32_t af[4][4], bf[4][2];
#pragma unroll
                for (int mi = 0; mi < 4; mi++) {
                    const int row = wm * 64 + mi * 16 + (lane & 15);
                    const int col = ks * 16 + (lane >> 4) * 8;
                    ldm_x4(af[mi], ab + (uint32_t)(row * APAD + col) * 2);
                }
#pragma unroll
                for (int ni = 0; ni < 4; ni++) {
                    const int krow = ks * 16 + (lane & 15);
                    const int ncol = wn * 32 + ni * 8;
                    ldm_x2_trans(bf[ni], bb + (uint32_t)(krow * BPAD + ncol) * 2);
                }
#pragma unroll
                for (int mi = 0; mi < 4; mi++)
#pragma unroll
                    for (int ni = 0; ni < 4; ni++)
                        mma_bf16(acc[mi][ni], af[mi], bf[ni]);
            }
        }
        __syncthreads();
    }

    const int g = lane >> 2, t4 = lane & 3;
#pragma unroll
    for (int mi = 0; mi < 4; mi++) {
        const int row = brow + wm * 64 + mi * 16 + g;
#pragma unroll
        for (int ni = 0; ni < 4; ni++) {
            const int col = bcol + wn * 32 + ni * 8 + 2 * t4;
            const float b0 = bias[col], b1 = bias[col + 1];
            if (MODE == 0) {
                float2 v0 = make_float2(acc[mi][ni][0] + b0, acc[mi][ni][1] + b1);
                float2 v1 = make_float2(acc[mi][ni][2] + b0, acc[mi][ni][3] + b1);
                *reinterpret_cast<float2*>(C + (size_t)row * N + col)       = v0;
                *reinterpret_cast<float2*>(C + (size_t)(row + 8) * N + col) = v1;
            } else {
                uint32_t h0, l0, h1, l1;
                split2((acc[mi][ni][0] + b0) * scale, (acc[mi][ni][1] + b1) * scale, h0, l0);
                split2((acc[mi][ni][2] + b0) * scale, (acc[mi][ni][3] + b1) * scale, h1, l1);
                *reinterpret_cast<uint32_t*>(&Ch[(size_t)row * N + col])       = h0;
                *reinterpret_cast<uint32_t*>(&Cl[(size_t)row * N + col])       = l0;
                *reinterpret_cast<uint32_t*>(&Ch[(size_t)(row + 8) * N + col]) = h1;
                *reinterpret_cast<uint32_t*>(&Cl[(size_t)(row + 8) * N + col]) = l1;
            }
        }
    }
}

// ---------------------------------------------------------------------------
// Tensor-core flash attention.
// 256 threads / 8 warps, QT=128 (warp w owns rows 16w..16w+15), KT=64.
// Grid (LQ/128, N_HEAD, BATCH). Q in registers (hi/lo A-frags, pre-scaled).
// S = 3-pass split QK^T; softmax on fragments; O = 3-pass split P*V.
// ---------------------------------------------------------------------------
#define SPAD 72   // bf16 row stride: 144B = 9*16B -> LDSM conflict-free

__global__ __launch_bounds__(256) void attn_mma(const int* __restrict__ mask)
{
    __shared__ __align__(16) __nv_bfloat16 Kh[64 * SPAD];
    __shared__ __align__(16) __nv_bfloat16 Kl[64 * SPAD];
    __shared__ __align__(16) __nv_bfloat16 Vh[64 * SPAD];
    __shared__ __align__(16) __nv_bfloat16 Vl[64 * SPAD];
    __shared__ float bias_s[64];

    const int tid  = threadIdx.x;
    const int warp = tid >> 5, lane = tid & 31;
    const int g    = lane >> 2, t4 = lane & 3;
    const int q0   = blockIdx.x * 128;
    const int h    = blockIdx.y;
    const int b    = blockIdx.z;

    const uint32_t khb = smem_u32(Kh), klb = smem_u32(Kl);
    const uint32_t vhb = smem_u32(Vh), vlb = smem_u32(Vl);

    // ---- load Q fragments (two phases through the K smem buffers) ----
    uint32_t qfh[4][4], qfl[4][4];
#pragma unroll
    for (int ph = 0; ph < 2; ph++) {
        const uint4* sqh = reinterpret_cast<const uint4*>(
            g_qh + ((size_t)b * LQ + q0 + ph * 64) * D_MODEL + h * D_H);
        const uint4* sql = reinterpret_cast<const uint4*>(
            g_ql + ((size_t)b * LQ + q0 + ph * 64) * D_MODEL + h * D_H);
#pragma unroll
        for (int i = 0; i < 2; i++) {
            const int idx = i * 256 + tid;           // 0..511
            const int r = idx >> 3, c = idx & 7;
            *reinterpret_cast<uint4*>(&Kh[r * SPAD + c * 8]) = sqh[r * 128 + c];
            *reinterpret_cast<uint4*>(&Kl[r * SPAD + c * 8]) = sql[r * 128 + c];
        }
        __syncthreads();
        if ((warp >> 2) == ph) {
            const int rbase = (warp & 3) * 16;
#pragma unroll
            for (int s = 0; s < 4; s++) {
                const uint32_t off =
                    (uint32_t)((rbase + (lane & 15)) * SPAD + (lane >> 4) * 8 + s * 16) * 2;
                ldm_x4(qfh[s], khb + off);
                ldm_x4(qfl[s], klb + off);
            }
        }
        __syncthreads();
    }

    float m0 = -1.0e30f, m1 = -1.0e30f, l0 = 0.0f, l1 = 0.0f;
    float o[8][4];
#pragma unroll
    for (int j = 0; j < 8; j++)
#pragma unroll
        for (int r = 0; r < 4; r++) o[j][r] = 0.0f;

    for (int kt = 0; kt < LK / 64; kt++) {
        __syncthreads();
        {
            const size_t rbase = ((size_t)b * LK + kt * 64) * D_MODEL + h * D_H;
            const uint4* skh = reinterpret_cast<const uint4*>(g_kh + rbase);
            const uint4* skl = reinterpret_cast<const uint4*>(g_kl + rbase);
            const uint4* svh = reinterpret_cast<const uint4*>(g_vh + rbase);
            const uint4* svl = reinterpret_cast<const uint4*>(g_vl + rbase);
#pragma unroll
            for (int i = 0; i < 2; i++) {
                const int idx = i * 256 + tid;
                const int r = idx >> 3, c = idx & 7;
                *reinterpret_cast<uint4*>(&Kh[r * SPAD + c * 8]) = skh[r * 128 + c];
                *reinterpret_cast<uint4*>(&Kl[r * SPAD + c * 8]) = skl[r * 128 + c];
                *reinterpret_cast<uint4*>(&Vh[r * SPAD + c * 8]) = svh[r * 128 + c];
                *reinterpret_cast<uint4*>(&Vl[r * SPAD + c * 8]) = svl[r * 128 + c];
            }
            if (tid < 64)
                bias_s[tid] = mask[(size_t)b * LK + kt * 64 + tid] ? -1.0e30f : 0.0f;
        }
        __syncthreads();

        // ---- S = Q K^T (3-pass split) ----
        float s[8][4];
#pragma unroll
        for (int j = 0; j < 8; j++)
#pragma unroll
            for (int r = 0; r < 4; r++) s[j][r] = 0.0f;

#pragma unroll
        for (int ks = 0; ks < 4; ks++) {
#pragma unroll
            for (int j = 0; j < 8; j++) {
                const uint32_t off =
                    (uint32_t)((j * 8 + (lane & 7)) * SPAD
                               + ks * 16 + 8 * ((lane >> 3) & 1)) * 2;
                uint32_t kb[2];
                ldm_x2(kb, khb + off);
                mma_bf16(s[j], qfh[ks], kb);
                mma_bf16(s[j], qfl[ks], kb);
                ldm_x2(kb, klb + off);
                mma_bf16(s[j], qfh[ks], kb);
            }
        }

        // ---- mask bias + online softmax on fragments ----
        float mx0 = -1.0e30f, mx1 = -1.0e30f;
#pragma unroll
        for (int j = 0; j < 8; j++) {
            const float b0 = bias_s[j * 8 + 2 * t4];
            const float b1 = bias_s[j * 8 + 2 * t4 + 1];
            s[j][0] += b0; s[j][1] += b1;
            s[j][2] += b0; s[j][3] += b1;
            mx0 = fmaxf(mx0, fmaxf(s[j][0], s[j][1]));
            mx1 = fmaxf(mx1, fmaxf(s[j][2], s[j][3]));
        }
        mx0 = fmaxf(mx0, __shfl_xor_sync(0xffffffffu, mx0, 1));
        mx0 = fmaxf(mx0, __shfl_xor_sync(0xffffffffu, mx0, 2));
        mx1 = fmaxf(mx1, __shfl_xor_sync(0xffffffffu, mx1, 1));
        mx1 = fmaxf(mx1, __shfl_xor_sync(0xffffffffu, mx1, 2));

        const float m0n = fmaxf(m0, mx0), m1n = fmaxf(m1, mx1);
        const float c0 = __expf(m0 - m0n), c1 = __expf(m1 - m1n);
        m0 = m0n; m1 = m1n;

        float sum0 = 0.0f, sum1 = 0.0f;
#pragma unroll
        for (int j = 0; j < 8; j++) {
            s[j][0] = __expf(s[j][0] - m0n);
            s[j][1] = __expf(s[j][1] - m0n);
            s[j][2] = __expf(s[j][2] - m1n);
            s[j][3] = __expf(s[j][3] - m1n);
            sum0 += s[j][0] + s[j][1];
            sum1 += s[j][2] + s[j][3];
        }
        sum0 += __shfl_xor_sync(0xffffffffu, sum0, 1);
        sum0 += __shfl_xor_sync(0xffffffffu, sum0, 2);
        sum1 += __shfl_xor_sync(0xffffffffu, sum1, 1);
        sum1 += __shfl_xor_sync(0xffffffffu, sum1, 2);
        l0 = l0 * c0 + sum0;
        l1 = l1 * c1 + sum1;

#pragma unroll
        for (int j = 0; j < 8; j++) {
            o[j][0] *= c0; o[j][1] *= c0;
            o[j][2] *= c1; o[j][3] *= c1;
        }

        // ---- O += P V (3-pass split; P fragments built from S) ----
#pragma unroll
        for (int ks = 0; ks < 4; ks++) {
            uint32_t pah[4], pal[4];
            split2(s[2 * ks][0],     s[2 * ks][1],     pah[0], pal[0]);
            split2(s[2 * ks][2],     s[2 * ks][3],     pah[1], pal[1]);
            split2(s[2 * ks + 1][0], s[2 * ks + 1][1], pah[2], pal[2]);
            split2(s[2 * ks + 1][2], s[2 * ks + 1][3], pah[3], pal[3]);
#pragma unroll
            for (int j = 0; j < 8; j++) {
                const uint32_t off =
                    (uint32_t)((ks * 16 + (lane & 15)) * SPAD + j * 8) * 2;
                uint32_t vb[2];
                ldm_x2_trans(vb, vhb + off);
                mma_bf16(o[j], pah, vb);
                mma_bf16(o[j], pal, vb);
                ldm_x2_trans(vb, vlb + off);
                mma_bf16(o[j], pah, vb);
            }
        }
    }

    // ---- normalize + write ----
    const float li0 = 1.0f / l0, li1 = 1.0f / l1;
    const int row0 = q0 + warp * 16 + g;
    float* out0 = g_attn + ((size_t)b * LQ + row0) * D_MODEL + h * D_H;
    float* out1 = out0 + 8 * D_MODEL;
#pragma unroll
    for (int j = 0; j < 8; j++) {
        const int col = j * 8 + 2 * t4;
        *reinterpret_cast<float2*>(out0 + col) =
            make_float2(o[j][0] * li0, o[j][1] * li0);
        *reinterpret_cast<float2*>(out1 + col) =
            make_float2(o[j][2] * li1, o[j][3] * li1);
    }
}

// ---------------------------------------------------------------------------
// Launch
// ---------------------------------------------------------------------------
extern "C" void kernel_launch(void* const* d_in, const int* in_sizes, int n_in,
                              void* d_out, int out_size)
{
    const float* q_in  = (const float*)d_in[0];
    const float* kv_in = (const float*)d_in[1];
    const int*   mask  = (const int*)  d_in[2];
    const float* W_Q   = (const float*)d_in[3];
    const float* b_Q   = (const float*)d_in[4];
    const float* W_K   = (const float*)d_in[5];
    const float* b_K   = (const float*)d_in[6];
    const float* W_V   = (const float*)d_in[7];
    const float* b_V   = (const float*)d_in[8];
    const float* W_O   = (const float*)d_in[9];
    const float* b_O   = (const float*)d_in[10];

    __nv_bfloat16 *qh, *ql, *kh, *kl, *vh, *vl;
    float* a_p;
    cudaGetSymbolAddress((void**)&qh, g_qh);
    cudaGetSymbolAddress((void**)&ql, g_ql);
    cudaGetSymbolAddress((void**)&kh, g_kh);
    cudaGetSymbolAddress((void**)&kl, g_kl);
    cudaGetSymbolAddress((void**)&vh, g_vh);
    cudaGetSymbolAddress((void**)&vl, g_vl);
    cudaGetSymbolAddress((void**)&a_p, g_attn);

    const dim3 thr(256);
    const dim3 gq(D_MODEL / 128, (BATCH * LQ) / 128);
    const dim3 gk(D_MODEL / 128, (BATCH * LK) / 128);

    gemm_mma<1><<<gq, thr>>>(q_in,  W_Q, b_Q, nullptr, qh, ql, 0.125f,
                             BATCH * LQ, D_MODEL, D_MODEL);
    gemm_mma<1><<<gk, thr>>>(kv_in, W_K, b_K, nullptr, kh, kl, 1.0f,
                             BATCH * LK, D_MODEL, D_MODEL);
    gemm_mma<1><<<gk, thr>>>(kv_in, W_V, b_V, nullptr, vh, vl, 1.0f,
                             BATCH * LK, D_MODEL, D_MODEL);

    const dim3 ga(LQ / 128, N_HEAD, BATCH);
    attn_mma<<<ga, 256>>>(mask);

    gemm_mma<0><<<gq, thr>>>(a_p, W_O, b_O, (float*)d_out, nullptr, nullptr, 1.0f,
                             BATCH * LQ, D_MODEL, D_MODEL);
}

// round 5
// speedup vs baseline: 4.5034x; 1.2684x over previous
#include <cuda_runtime.h>
#include <cuda_bf16.h>
#include <stdint.h>
#include <math.h>

#define D_MODEL 1024
#define N_HEAD  16
#define D_H     64
#define BATCH   4
#define LQ      1024
#define LK      2048

// ---------------------------------------------------------------------------
// Scratch (no cudaMalloc allowed)
// ---------------------------------------------------------------------------
// pre-split inputs / weights
__device__ __nv_bfloat16 g_qinh[(size_t)BATCH * LQ * D_MODEL];
__device__ __nv_bfloat16 g_qinl[(size_t)BATCH * LQ * D_MODEL];
__device__ __nv_bfloat16 g_kvinh[(size_t)BATCH * LK * D_MODEL];
__device__ __nv_bfloat16 g_kvinl[(size_t)BATCH * LK * D_MODEL];
__device__ __nv_bfloat16 g_wqh[(size_t)D_MODEL * D_MODEL];
__device__ __nv_bfloat16 g_wql[(size_t)D_MODEL * D_MODEL];
__device__ __nv_bfloat16 g_wkh[(size_t)D_MODEL * D_MODEL];
__device__ __nv_bfloat16 g_wkl[(size_t)D_MODEL * D_MODEL];
__device__ __nv_bfloat16 g_wvh[(size_t)D_MODEL * D_MODEL];
__device__ __nv_bfloat16 g_wvl[(size_t)D_MODEL * D_MODEL];
__device__ __nv_bfloat16 g_woh[(size_t)D_MODEL * D_MODEL];
__device__ __nv_bfloat16 g_wol[(size_t)D_MODEL * D_MODEL];
// projections (split) + attn output (split)
__device__ __nv_bfloat16 g_qh[(size_t)BATCH * LQ * D_MODEL];
__device__ __nv_bfloat16 g_ql[(size_t)BATCH * LQ * D_MODEL];
__device__ __nv_bfloat16 g_kh[(size_t)BATCH * LK * D_MODEL];
__device__ __nv_bfloat16 g_kl[(size_t)BATCH * LK * D_MODEL];
__device__ __nv_bfloat16 g_vh[(size_t)BATCH * LK * D_MODEL];
__device__ __nv_bfloat16 g_vl[(size_t)BATCH * LK * D_MODEL];
__device__ __nv_bfloat16 g_ah[(size_t)BATCH * LQ * D_MODEL];
__device__ __nv_bfloat16 g_al[(size_t)BATCH * LQ * D_MODEL];
__device__ float         g_biasf[(size_t)BATCH * LK];

// ---------------------------------------------------------------------------
// Helpers
// ---------------------------------------------------------------------------
__device__ __forceinline__ uint32_t smem_u32(const void* p) {
    uint32_t a;
    asm("{ .reg .u64 t; cvta.to.shared.u64 t, %1; cvt.u32.u64 %0, t; }"
        : "=r"(a) : "l"(p));
    return a;
}
__device__ __forceinline__ void cp16(uint32_t d, const void* g) {
    asm volatile("cp.async.cg.shared.global [%0], [%1], 16;" :: "r"(d), "l"(g));
}
__device__ __forceinline__ void cp_commit() {
    asm volatile("cp.async.commit_group;" ::: "memory");
}
__device__ __forceinline__ void ldm_x4(uint32_t* r, uint32_t addr) {
    asm volatile("ldmatrix.sync.aligned.m8n8.x4.shared.b16 {%0,%1,%2,%3}, [%4];"
                 : "=r"(r[0]), "=r"(r[1]), "=r"(r[2]), "=r"(r[3]) : "r"(addr));
}
__device__ __forceinline__ void ldm_x4_trans(uint32_t* r, uint32_t addr) {
    asm volatile("ldmatrix.sync.aligned.m8n8.x4.trans.shared.b16 {%0,%1,%2,%3}, [%4];"
                 : "=r"(r[0]), "=r"(r[1]), "=r"(r[2]), "=r"(r[3]) : "r"(addr));
}
__device__ __forceinline__ void mma_bf16(float* c, const uint32_t* a, const uint32_t* b) {
    asm volatile(
        "mma.sync.aligned.m16n8k16.row.col.f32.bf16.bf16.f32 "
        "{%0,%1,%2,%3}, {%4,%5,%6,%7}, {%8,%9}, {%0,%1,%2,%3};"
        : "+f"(c[0]), "+f"(c[1]), "+f"(c[2]), "+f"(c[3])
        : "r"(a[0]), "r"(a[1]), "r"(a[2]), "r"(a[3]), "r"(b[0]), "r"(b[1]));
}
__device__ __forceinline__ void split2(float a, float b, uint32_t& hi, uint32_t& lo) {
    __nv_bfloat162 h2 = __float22bfloat162_rn(make_float2(a, b));
    float2 hf = __bfloat1622float2(h2);
    __nv_bfloat162 l2 = __float22bfloat162_rn(make_float2(a - hf.x, b - hf.y));
    hi = *reinterpret_cast<uint32_t*>(&h2);
    lo = *reinterpret_cast<uint32_t*>(&l2);
}

// ---------------------------------------------------------------------------
// Pre-split f32 -> bf16 hi/lo
// ---------------------------------------------------------------------------
__global__ __launch_bounds__(256) void split_kernel(
    const float* __restrict__ src, __nv_bfloat16* __restrict__ dh,
    __nv_bfloat16* __restrict__ dl, int n4)
{
    const int i = blockIdx.x * 256 + threadIdx.x;
    if (i < n4) {
        float4 v = reinterpret_cast<const float4*>(src)[i];
        uint32_t h0, l0, h1, l1;
        split2(v.x, v.y, h0, l0);
        split2(v.z, v.w, h1, l1);
        reinterpret_cast<uint2*>(dh)[i] = make_uint2(h0, h1);
        reinterpret_cast<uint2*>(dl)[i] = make_uint2(l0, l1);
    }
}

__global__ __launch_bounds__(256) void mask_bias_kernel(
    const int* __restrict__ mask, float* __restrict__ bias, int n)
{
    const int i = blockIdx.x * 256 + threadIdx.x;
    if (i < n) bias[i] = mask[i] ? -1.0e30f : 0.0f;
}

// ---------------------------------------------------------------------------
// Pipelined bf16-split GEMM on pre-split inputs.
// C[M,N] = A@W + bias.  128x128 tile, BK=32, 256 thr, 2-stage cp.async.
// MODE 0: fp32 out.  MODE 1: split-bf16 out, (acc+bias)*scale.
// ---------------------------------------------------------------------------
#define G_STG 37888   // per-stage: Ah 10240 + Al 10240 + Bh 8704 + Bl 8704

template <int MODE>
__global__ __launch_bounds__(256) void gemm_bb(
    const __nv_bfloat16* __restrict__ Ahg, const __nv_bfloat16* __restrict__ Alg,
    const __nv_bfloat16* __restrict__ Whg, const __nv_bfloat16* __restrict__ Wlg,
    const float* __restrict__ bias, float* __restrict__ C,
    __nv_bfloat16* __restrict__ Ch, __nv_bfloat16* __restrict__ Cl,
    float scale, int M, int K, int N)
{
    extern __shared__ __align__(16) char dsm[];
    const uint32_t sb = smem_u32(dsm);

    const int tid  = threadIdx.x;
    const int warp = tid >> 5, lane = tid & 31;
    const int wm   = warp >> 2, wn = warp & 3;
    const int brow = blockIdx.y * 128;
    const int bcol = blockIdx.x * 128;

    float acc[4][4][4];
#pragma unroll
    for (int mi = 0; mi < 4; mi++)
#pragma unroll
        for (int ni = 0; ni < 4; ni++)
#pragma unroll
            for (int r = 0; r < 4; r++) acc[mi][ni][r] = 0.0f;

    // issue one stage of loads: A rows 80B-stride (APAD 40), B rows 272B (BPAD 136)
    auto issue = [&](int kt, int s) {
        const int k0 = kt * 32;
        const uint32_t st = sb + s * G_STG;
#pragma unroll
        for (int i = 0; i < 2; i++) {
            const int idx = i * 256 + tid;
            const int r = idx >> 2, c = idx & 3;
            const uint32_t d = st + r * 80 + c * 16;
            const size_t go = (size_t)(brow + r) * K + k0 + c * 8;
            cp16(d,         Ahg + go);
            cp16(d + 10240, Alg + go);
        }
#pragma unroll
        for (int i = 0; i < 2; i++) {
            const int idx = i * 256 + tid;
            const int r = idx >> 4, c = idx & 15;
            const uint32_t d = st + 20480 + r * 272 + c * 16;
            const size_t go = (size_t)(k0 + r) * N + bcol + c * 8;
            cp16(d,        Whg + go);
            cp16(d + 8704, Wlg + go);
        }
        cp_commit();
    };

    const int NK = K / 32;
    issue(0, 0);
    for (int kt = 0; kt < NK; kt++) {
        const int s = kt & 1;
        if (kt + 1 < NK) {
            issue(kt + 1, s ^ 1);
            asm volatile("cp.async.wait_group 1;" ::: "memory");
        } else {
            asm volatile("cp.async.wait_group 0;" ::: "memory");
        }
        __syncthreads();

        const uint32_t ah = sb + s * G_STG;
        const uint32_t al = ah + 10240;
        const uint32_t bh = ah + 20480;
        const uint32_t bl = ah + 29184;

#pragma unroll
        for (int p = 0; p < 3; p++) {
            const uint32_t ab = (p == 2) ? al : ah;
            const uint32_t bb = (p == 1) ? bl : bh;
#pragma unroll
            for (int ks = 0; ks < 2; ks++) {
                uint32_t af[4][4], bf[2][4];
#pragma unroll
                for (int mi = 0; mi < 4; mi++) {
                    const int row = wm * 64 + mi * 16 + (lane & 15);
                    const int col = ks * 16 + (lane >> 4) * 8;
                    ldm_x4(af[mi], ab + (uint32_t)(row * 40 + col) * 2);
                }
#pragma unroll
                for (int np = 0; np < 2; np++) {
                    const int krow = ks * 16 + (lane & 15);
                    const int ncol = wn * 32 + np * 16 + ((lane >> 4) & 1) * 8;
                    ldm_x4_trans(bf[np], bb + (uint32_t)(krow * 136 + ncol) * 2);
                }
#pragma unroll
                for (int mi = 0; mi < 4; mi++)
#pragma unroll
                    for (int ni = 0; ni < 4; ni++)
                        mma_bf16(acc[mi][ni], af[mi], &bf[ni >> 1][(ni & 1) * 2]);
            }
        }
        __syncthreads();
    }

    const int g = lane >> 2, t4 = lane & 3;
#pragma unroll
    for (int mi = 0; mi < 4; mi++) {
        const int row = brow + wm * 64 + mi * 16 + g;
#pragma unroll
        for (int ni = 0; ni < 4; ni++) {
            const int col = bcol + wn * 32 + ni * 8 + 2 * t4;
            const float b0 = bias[col], b1 = bias[col + 1];
            if (MODE == 0) {
                *reinterpret_cast<float2*>(C + (size_t)row * N + col) =
                    make_float2(acc[mi][ni][0] + b0, acc[mi][ni][1] + b1);
                *reinterpret_cast<float2*>(C + (size_t)(row + 8) * N + col) =
                    make_float2(acc[mi][ni][2] + b0, acc[mi][ni][3] + b1);
            } else {
                uint32_t h0, l0, h1, l1;
                split2((acc[mi][ni][0] + b0) * scale, (acc[mi][ni][1] + b1) * scale, h0, l0);
                split2((acc[mi][ni][2] + b0) * scale, (acc[mi][ni][3] + b1) * scale, h1, l1);
                *reinterpret_cast<uint32_t*>(&Ch[(size_t)row * N + col])       = h0;
                *reinterpret_cast<uint32_t*>(&Cl[(size_t)row * N + col])       = l0;
                *reinterpret_cast<uint32_t*>(&Ch[(size_t)(row + 8) * N + col]) = h1;
                *reinterpret_cast<uint32_t*>(&Cl[(size_t)(row + 8) * N + col]) = l1;
            }
        }
    }
}

// ---------------------------------------------------------------------------
// Tensor-core flash attention, 2-stage cp.async pipeline, x4 ldmatrix.
// 256 thr / 8 warps, QT=128 (warp w -> rows 16w..16w+15), KT=64.
// Writes split-bf16 output for the O-projection.
// ---------------------------------------------------------------------------
#define A_TS  9216            // one 64x(SPAD=72) bf16 tile = 64*144 B
#define A_STG (4 * A_TS)      // Kh,Kl,Vh,Vl per stage = 36864
#define A_BOFF (2 * A_STG)    // bias stages at 73728 (+ s*256)
#define A_DSM (A_BOFF + 512)

__global__ __launch_bounds__(256) void attn_mma(const float* __restrict__ biasg)
{
    extern __shared__ __align__(16) char dsm[];
    const uint32_t sb = smem_u32(dsm);

    const int tid  = threadIdx.x;
    const int warp = tid >> 5, lane = tid & 31;
    const int g    = lane >> 2, t4 = lane & 3;
    const int q0   = blockIdx.x * 128;
    const int h    = blockIdx.y;
    const int b    = blockIdx.z;

    // ---- Q fragments via stage-0 Kh/Kl area (plain 16B loads) ----
    uint32_t qfh[4][4], qfl[4][4];
#pragma unroll
    for (int ph = 0; ph < 2; ph++) {
        const size_t qbase = ((size_t)b * LQ + q0 + ph * 64) * D_MODEL + h * D_H;
#pragma unroll
        for (int i = 0; i < 2; i++) {
            const int r = i * 32 + (tid >> 3), c = tid & 7;
            const size_t go = qbase + (size_t)r * D_MODEL + c * 8;
            *reinterpret_cast<uint4*>(dsm + r * 144 + c * 16) =
                *reinterpret_cast<const uint4*>(g_qh + go);
            *reinterpret_cast<uint4*>(dsm + A_TS + r * 144 + c * 16) =
                *reinterpret_cast<const uint4*>(g_ql + go);
        }
        __syncthreads();
        if ((warp >> 2) == ph) {
            const int rbase = (warp & 3) * 16;
#pragma unroll
            for (int s = 0; s < 4; s++) {
                const uint32_t off =
                    (uint32_t)((rbase + (lane & 15)) * 72 + (lane >> 4) * 8 + s * 16) * 2;
                ldm_x4(qfh[s], sb + off);
                ldm_x4(qfl[s], sb + A_TS + off);
            }
        }
        __syncthreads();
    }

    // ---- pipeline ----
    auto issue = [&](int kt, int s) {
        const size_t kvbase = ((size_t)b * LK + kt * 64) * D_MODEL + h * D_H;
        const uint32_t st = sb + s * A_STG;
#pragma unroll
        for (int i = 0; i < 8; i++) {
            const int r = ((i & 1) * 256 + tid) >> 3;   // 0..63
            const int c = tid & 7;
            const size_t go = kvbase + (size_t)r * D_MODEL + c * 8;
            const uint32_t d = st + (i >> 1) * A_TS + r * 144 + c * 16;
            const __nv_bfloat16* src =
                (i >> 1) == 0 ? g_kh : (i >> 1) == 1 ? g_kl
                              : (i >> 1) == 2 ? g_vh : g_vl;
            cp16(d, src + go);
        }
        if (tid < 16)
            cp16(sb + A_BOFF + s * 256 + tid * 16,
                 biasg + (size_t)b * LK + kt * 64 + tid * 4);
        cp_commit();
    };

    float m0 = -1.0e30f, m1 = -1.0e30f, l0 = 0.0f, l1 = 0.0f;
    float o[8][4];
#pragma unroll
    for (int j = 0; j < 8; j++)
#pragma unroll
        for (int r = 0; r < 4; r++) o[j][r] = 0.0f;

    const int NK = LK / 64;
    issue(0, 0);
    for (int kt = 0; kt < NK; kt++) {
        const int st = kt & 1;
        if (kt + 1 < NK) {
            issue(kt + 1, st ^ 1);
            asm volatile("cp.async.wait_group 1;" ::: "memory");
        } else {
            asm volatile("cp.async.wait_group 0;" ::: "memory");
        }
        __syncthreads();

        const uint32_t khb = sb + st * A_STG;
        const uint32_t klb = khb + A_TS;
        const uint32_t vhb = khb + 2 * A_TS;
        const uint32_t vlb = khb + 3 * A_TS;
        const float* bias_s = reinterpret_cast<const float*>(dsm + A_BOFF + st * 256);

        // ---- S = Q K^T (3-pass split) ----
        float s[8][4];
#pragma unroll
        for (int j = 0; j < 8; j++)
#pragma unroll
            for (int r = 0; r < 4; r++) s[j][r] = 0.0f;

#pragma unroll
        for (int ks = 0; ks < 4; ks++) {
#pragma unroll
            for (int jp = 0; jp < 4; jp++) {
                const int row = jp * 16 + ((lane >> 4) & 1) * 8 + (lane & 7);
                const int col = ks * 16 + ((lane >> 3) & 1) * 8;
                const uint32_t off = (uint32_t)(row * 72 + col) * 2;
                uint32_t kh4[4], kl4[4];
                ldm_x4(kh4, khb + off);
                ldm_x4(kl4, klb + off);
                mma_bf16(s[2 * jp],     qfh[ks], kh4);
                mma_bf16(s[2 * jp],     qfl[ks], kh4);
                mma_bf16(s[2 * jp],     qfh[ks], kl4);
                mma_bf16(s[2 * jp + 1], qfh[ks], kh4 + 2);
                mma_bf16(s[2 * jp + 1], qfl[ks], kh4 + 2);
                mma_bf16(s[2 * jp + 1], qfh[ks], kl4 + 2);
            }
        }

        // ---- mask bias + online softmax on fragments ----
        float mx0 = -1.0e30f, mx1 = -1.0e30f;
#pragma unroll
        for (int j = 0; j < 8; j++) {
            const float b0 = bias_s[j * 8 + 2 * t4];
            const float b1 = bias_s[j * 8 + 2 * t4 + 1];
            s[j][0] += b0; s[j][1] += b1;
            s[j][2] += b0; s[j][3] += b1;
            mx0 = fmaxf(mx0, fmaxf(s[j][0], s[j][1]));
            mx1 = fmaxf(mx1, fmaxf(s[j][2], s[j][3]));
        }
        mx0 = fmaxf(mx0, __shfl_xor_sync(0xffffffffu, mx0, 1));
        mx0 = fmaxf(mx0, __shfl_xor_sync(0xffffffffu, mx0, 2));
        mx1 = fmaxf(mx1, __shfl_xor_sync(0xffffffffu, mx1, 1));
        mx1 = fmaxf(mx1, __shfl_xor_sync(0xffffffffu, mx1, 2));

        const float m0n = fmaxf(m0, mx0), m1n = fmaxf(m1, mx1);
        const float c0 = __expf(m0 - m0n), c1 = __expf(m1 - m1n);
        m0 = m0n; m1 = m1n;

        float sum0 = 0.0f, sum1 = 0.0f;
#pragma unroll
        for (int j = 0; j < 8; j++) {
            s[j][0] = __expf(s[j][0] - m0n);
            s[j][1] = __expf(s[j][1] - m0n);
            s[j][2] = __expf(s[j][2] - m1n);
            s[j][3] = __expf(s[j][3] - m1n);
            sum0 += s[j][0] + s[j][1];
            sum1 += s[j][2] + s[j][3];
        }
        sum0 += __shfl_xor_sync(0xffffffffu, sum0, 1);
        sum0 += __shfl_xor_sync(0xffffffffu, sum0, 2);
        sum1 += __shfl_xor_sync(0xffffffffu, sum1, 1);
        sum1 += __shfl_xor_sync(0xffffffffu, sum1, 2);
        l0 = l0 * c0 + sum0;
        l1 = l1 * c1 + sum1;

#pragma unroll
        for (int j = 0; j < 8; j++) {
            o[j][0] *= c0; o[j][1] *= c0;
            o[j][2] *= c1; o[j][3] *= c1;
        }

        // ---- O += P V (3-pass split) ----
#pragma unroll
        for (int ks = 0; ks < 4; ks++) {
            uint32_t pah[4], pal[4];
            split2(s[2 * ks][0],     s[2 * ks][1],     pah[0], pal[0]);
            split2(s[2 * ks][2],     s[2 * ks][3],     pah[1], pal[1]);
            split2(s[2 * ks + 1][0], s[2 * ks + 1][1], pah[2], pal[2]);
            split2(s[2 * ks + 1][2], s[2 * ks + 1][3], pah[3], pal[3]);
#pragma unroll
            for (int jp = 0; jp < 4; jp++) {
                const int row = ks * 16 + (lane & 15);
                const int col = jp * 16 + ((lane >> 4) & 1) * 8;
                const uint32_t off = (uint32_t)(row * 72 + col) * 2;
                uint32_t vh4[4], vl4[4];
                ldm_x4_trans(vh4, vhb + off);
                ldm_x4_trans(vl4, vlb + off);
                mma_bf16(o[2 * jp],     pah, vh4);
                mma_bf16(o[2 * jp],     pal, vh4);
                mma_bf16(o[2 * jp],     pah, vl4);
                mma_bf16(o[2 * jp + 1], pah, vh4 + 2);
                mma_bf16(o[2 * jp + 1], pal, vh4 + 2);
                mma_bf16(o[2 * jp + 1], pah, vl4 + 2);
            }
        }
        __syncthreads();
    }

    // ---- normalize + write split-bf16 output ----
    const float li0 = 1.0f / l0, li1 = 1.0f / l1;
    const int row0 = q0 + warp * 16 + g;
    const size_t base0 = ((size_t)b * LQ + row0) * D_MODEL + h * D_H;
    const size_t base1 = base0 + (size_t)8 * D_MODEL;
#pragma unroll
    for (int j = 0; j < 8; j++) {
        const int col = j * 8 + 2 * t4;
        uint32_t h0, l0r, h1, l1r;
        split2(o[j][0] * li0, o[j][1] * li0, h0, l0r);
        split2(o[j][2] * li1, o[j][3] * li1, h1, l1r);
        *reinterpret_cast<uint32_t*>(&g_ah[base0 + col]) = h0;
        *reinterpret_cast<uint32_t*>(&g_al[base0 + col]) = l0r;
        *reinterpret_cast<uint32_t*>(&g_ah[base1 + col]) = h1;
        *reinterpret_cast<uint32_t*>(&g_al[base1 + col]) = l1r;
    }
}

// ---------------------------------------------------------------------------
// Launch
// ---------------------------------------------------------------------------
extern "C" void kernel_launch(void* const* d_in, const int* in_sizes, int n_in,
                              void* d_out, int out_size)
{
    const float* q_in  = (const float*)d_in[0];
    const float* kv_in = (const float*)d_in[1];
    const int*   mask  = (const int*)  d_in[2];
    const float* W_Q   = (const float*)d_in[3];
    const float* b_Q   = (const float*)d_in[4];
    const float* W_K   = (const float*)d_in[5];
    const float* b_K   = (const float*)d_in[6];
    const float* W_V   = (const float*)d_in[7];
    const float* b_V   = (const float*)d_in[8];
    const float* W_O   = (const float*)d_in[9];
    const float* b_O   = (const float*)d_in[10];

    __nv_bfloat16 *qinh, *qinl, *kvinh, *kvinl;
    __nv_bfloat16 *wqh, *wql, *wkh, *wkl, *wvh, *wvl, *woh, *wol;
    __nv_bfloat16 *qh, *ql, *kh, *kl, *vh, *vl, *ah, *al;
    float* biasf;
    cudaGetSymbolAddress((void**)&qinh,  g_qinh);
    cudaGetSymbolAddress((void**)&qinl,  g_qinl);
    cudaGetSymbolAddress((void**)&kvinh, g_kvinh);
    cudaGetSymbolAddress((void**)&kvinl, g_kvinl);
    cudaGetSymbolAddress((void**)&wqh, g_wqh);  cudaGetSymbolAddress((void**)&wql, g_wql);
    cudaGetSymbolAddress((void**)&wkh, g_wkh);  cudaGetSymbolAddress((void**)&wkl, g_wkl);
    cudaGetSymbolAddress((void**)&wvh, g_wvh);  cudaGetSymbolAddress((void**)&wvl, g_wvl);
    cudaGetSymbolAddress((void**)&woh, g_woh);  cudaGetSymbolAddress((void**)&wol, g_wol);
    cudaGetSymbolAddress((void**)&qh, g_qh);    cudaGetSymbolAddress((void**)&ql, g_ql);
    cudaGetSymbolAddress((void**)&kh, g_kh);    cudaGetSymbolAddress((void**)&kl, g_kl);
    cudaGetSymbolAddress((void**)&vh, g_vh);    cudaGetSymbolAddress((void**)&vl, g_vl);
    cudaGetSymbolAddress((void**)&ah, g_ah);    cudaGetSymbolAddress((void**)&al, g_al);
    cudaGetSymbolAddress((void**)&biasf, g_biasf);

    static bool attr_done = false;
    const int GDSM = 2 * G_STG;           // 75776
    cudaFuncSetAttribute(gemm_bb<0>, cudaFuncAttributeMaxDynamicSharedMemorySize, GDSM);
    cudaFuncSetAttribute(gemm_bb<1>, cudaFuncAttributeMaxDynamicSharedMemorySize, GDSM);
    cudaFuncSetAttribute(attn_mma,   cudaFuncAttributeMaxDynamicSharedMemorySize, A_DSM);
    (void)attr_done;

    // ---- pre-split ----
    const int nq4  = BATCH * LQ * D_MODEL / 4;
    const int nkv4 = BATCH * LK * D_MODEL / 4;
    const int nw4  = D_MODEL * D_MODEL / 4;
    split_kernel<<<nq4 / 256, 256>>>(q_in,  qinh,  qinl,  nq4);
    split_kernel<<<nkv4 / 256, 256>>>(kv_in, kvinh, kvinl, nkv4);
    split_kernel<<<nw4 / 256, 256>>>(W_Q, wqh, wql, nw4);
    split_kernel<<<nw4 / 256, 256>>>(W_K, wkh, wkl, nw4);
    split_kernel<<<nw4 / 256, 256>>>(W_V, wvh, wvl, nw4);
    split_kernel<<<nw4 / 256, 256>>>(W_O, woh, wol, nw4);
    mask_bias_kernel<<<(BATCH * LK) / 256, 256>>>(mask, biasf, BATCH * LK);

    // ---- projections ----
    const dim3 thr(256);
    const dim3 gq(D_MODEL / 128, (BATCH * LQ) / 128);
    const dim3 gk(D_MODEL / 128, (BATCH * LK) / 128);
    gemm_bb<1><<<gq, thr, GDSM>>>(qinh, qinl, wqh, wql, b_Q, nullptr, qh, ql,
                                  0.125f, BATCH * LQ, D_MODEL, D_MODEL);
    gemm_bb<1><<<gk, thr, GDSM>>>(kvinh, kvinl, wkh, wkl, b_K, nullptr, kh, kl,
                                  1.0f, BATCH * LK, D_MODEL, D_MODEL);
    gemm_bb<1><<<gk, thr, GDSM>>>(kvinh, kvinl, wvh, wvl, b_V, nullptr, vh, vl,
                                  1.0f, BATCH * LK, D_MODEL, D_MODEL);

    // ---- attention ----
    const dim3 ga(LQ / 128, N_HEAD, BATCH);
    attn_mma<<<ga, 256, A_DSM>>>(biasf);

    // ---- output projection ----
    gemm_bb<0><<<gq, thr, GDSM>>>(ah, al, woh, wol, b_O, (float*)d_out,
                                  nullptr, nullptr, 1.0f, BATCH * LQ, D_MODEL, D_MODEL);
}

// round 6
// speedup vs baseline: 5.4083x; 1.2009x over previous
#include <cuda_runtime.h>
#include <cuda_bf16.h>
#include <stdint.h>
#include <math.h>

#define D_MODEL 1024
#define N_HEAD  16
#define D_H     64
#define BATCH   4
#define LQ      1024
#define LK      2048

// ---------------------------------------------------------------------------
// Scratch (no cudaMalloc allowed)
// ---------------------------------------------------------------------------
__device__ __nv_bfloat16 g_qinh[(size_t)BATCH * LQ * D_MODEL];
__device__ __nv_bfloat16 g_qinl[(size_t)BATCH * LQ * D_MODEL];
__device__ __nv_bfloat16 g_kvinh[(size_t)BATCH * LK * D_MODEL];
__device__ __nv_bfloat16 g_kvinl[(size_t)BATCH * LK * D_MODEL];
__device__ __nv_bfloat16 g_wqh[(size_t)D_MODEL * D_MODEL];
__device__ __nv_bfloat16 g_wql[(size_t)D_MODEL * D_MODEL];
__device__ __nv_bfloat16 g_wkh[(size_t)D_MODEL * D_MODEL];
__device__ __nv_bfloat16 g_wkl[(size_t)D_MODEL * D_MODEL];
__device__ __nv_bfloat16 g_wvh[(size_t)D_MODEL * D_MODEL];
__device__ __nv_bfloat16 g_wvl[(size_t)D_MODEL * D_MODEL];
__device__ __nv_bfloat16 g_woh[(size_t)D_MODEL * D_MODEL];
__device__ __nv_bfloat16 g_wol[(size_t)D_MODEL * D_MODEL];
__device__ __nv_bfloat16 g_qh[(size_t)BATCH * LQ * D_MODEL];
__device__ __nv_bfloat16 g_ql[(size_t)BATCH * LQ * D_MODEL];
__device__ __nv_bfloat16 g_kh[(size_t)BATCH * LK * D_MODEL];
__device__ __nv_bfloat16 g_kl[(size_t)BATCH * LK * D_MODEL];
__device__ __nv_bfloat16 g_vh[(size_t)BATCH * LK * D_MODEL];
__device__ __nv_bfloat16 g_vl[(size_t)BATCH * LK * D_MODEL];
__device__ __nv_bfloat16 g_ah[(size_t)BATCH * LQ * D_MODEL];
__device__ __nv_bfloat16 g_al[(size_t)BATCH * LQ * D_MODEL];
__device__ float         g_biasf[(size_t)BATCH * LK];

// ---------------------------------------------------------------------------
// Helpers
// ---------------------------------------------------------------------------
__device__ __forceinline__ uint32_t smem_u32(const void* p) {
    uint32_t a;
    asm("{ .reg .u64 t; cvta.to.shared.u64 t, %1; cvt.u32.u64 %0, t; }"
        : "=r"(a) : "l"(p));
    return a;
}
__device__ __forceinline__ void cp16(uint32_t d, const void* g) {
    asm volatile("cp.async.cg.shared.global [%0], [%1], 16;" :: "r"(d), "l"(g));
}
__device__ __forceinline__ void cp_commit() {
    asm volatile("cp.async.commit_group;" ::: "memory");
}
__device__ __forceinline__ void ldm_x4(uint32_t* r, uint32_t addr) {
    asm volatile("ldmatrix.sync.aligned.m8n8.x4.shared.b16 {%0,%1,%2,%3}, [%4];"
                 : "=r"(r[0]), "=r"(r[1]), "=r"(r[2]), "=r"(r[3]) : "r"(addr));
}
__device__ __forceinline__ void ldm_x4_trans(uint32_t* r, uint32_t addr) {
    asm volatile("ldmatrix.sync.aligned.m8n8.x4.trans.shared.b16 {%0,%1,%2,%3}, [%4];"
                 : "=r"(r[0]), "=r"(r[1]), "=r"(r[2]), "=r"(r[3]) : "r"(addr));
}
__device__ __forceinline__ void mma_bf16(float* c, const uint32_t* a, const uint32_t* b) {
    asm volatile(
        "mma.sync.aligned.m16n8k16.row.col.f32.bf16.bf16.f32 "
        "{%0,%1,%2,%3}, {%4,%5,%6,%7}, {%8,%9}, {%0,%1,%2,%3};"
        : "+f"(c[0]), "+f"(c[1]), "+f"(c[2]), "+f"(c[3])
        : "r"(a[0]), "r"(a[1]), "r"(a[2]), "r"(a[3]), "r"(b[0]), "r"(b[1]));
}
__device__ __forceinline__ void split2(float a, float b, uint32_t& hi, uint32_t& lo) {
    __nv_bfloat162 h2 = __float22bfloat162_rn(make_float2(a, b));
    float2 hf = __bfloat1622float2(h2);
    __nv_bfloat162 l2 = __float22bfloat162_rn(make_float2(a - hf.x, b - hf.y));
    hi = *reinterpret_cast<uint32_t*>(&h2);
    lo = *reinterpret_cast<uint32_t*>(&l2);
}

// ---------------------------------------------------------------------------
// Pre-split kernels
// ---------------------------------------------------------------------------
__global__ __launch_bounds__(256) void split_kernel(
    const float* __restrict__ src, __nv_bfloat16* __restrict__ dh,
    __nv_bfloat16* __restrict__ dl, int n4)
{
    const int i = blockIdx.x * 256 + threadIdx.x;
    if (i < n4) {
        float4 v = reinterpret_cast<const float4*>(src)[i];
        uint32_t h0, l0, h1, l1;
        split2(v.x, v.y, h0, l0);
        split2(v.z, v.w, h1, l1);
        reinterpret_cast<uint2*>(dh)[i] = make_uint2(h0, h1);
        reinterpret_cast<uint2*>(dl)[i] = make_uint2(l0, l1);
    }
}

// fused 4-weight split: blockIdx.y selects the tensor
__global__ __launch_bounds__(256) void split4_kernel(
    const float* __restrict__ s0, const float* __restrict__ s1,
    const float* __restrict__ s2, const float* __restrict__ s3,
    __nv_bfloat16* __restrict__ h0p, __nv_bfloat16* __restrict__ l0p,
    __nv_bfloat16* __restrict__ h1p, __nv_bfloat16* __restrict__ l1p,
    __nv_bfloat16* __restrict__ h2p, __nv_bfloat16* __restrict__ l2p,
    __nv_bfloat16* __restrict__ h3p, __nv_bfloat16* __restrict__ l3p,
    int n4)
{
    const int i = blockIdx.x * 256 + threadIdx.x;
    if (i >= n4) return;
    const float* src; __nv_bfloat16 *dh, *dl;
    switch (blockIdx.y) {
        case 0: src = s0; dh = h0p; dl = l0p; break;
        case 1: src = s1; dh = h1p; dl = l1p; break;
        case 2: src = s2; dh = h2p; dl = l2p; break;
        default: src = s3; dh = h3p; dl = l3p; break;
    }
    float4 v = reinterpret_cast<const float4*>(src)[i];
    uint32_t h0, l0, h1, l1;
    split2(v.x, v.y, h0, l0);
    split2(v.z, v.w, h1, l1);
    reinterpret_cast<uint2*>(dh)[i] = make_uint2(h0, h1);
    reinterpret_cast<uint2*>(dl)[i] = make_uint2(l0, l1);
}

__global__ __launch_bounds__(256) void mask_bias_kernel(
    const int* __restrict__ mask, float* __restrict__ bias, int n)
{
    const int i = blockIdx.x * 256 + threadIdx.x;
    if (i < n) bias[i] = mask[i] ? -1.0e30f : 0.0f;
}

// ---------------------------------------------------------------------------
// Pipelined bf16-split GEMM (4-stage cp.async, fragment-reuse mainloop).
// MODE 0: fp32 out.  MODE 1: split-bf16 out.  MODE 2: fused K|V (bx selects).
// ---------------------------------------------------------------------------
#define G_STG 37888   // Ah 10240 + Al 10240 + Bh 8704 + Bl 8704
#define GDSM  (4 * G_STG)

template <int MODE>
__global__ __launch_bounds__(256) void gemm_bb(
    const __nv_bfloat16* __restrict__ Ahg, const __nv_bfloat16* __restrict__ Alg,
    const __nv_bfloat16* __restrict__ Whg, const __nv_bfloat16* __restrict__ Wlg,
    const float* __restrict__ bias, float* __restrict__ C,
    __nv_bfloat16* __restrict__ Ch, __nv_bfloat16* __restrict__ Cl,
    const __nv_bfloat16* __restrict__ Whg2, const __nv_bfloat16* __restrict__ Wlg2,
    const float* __restrict__ bias2,
    __nv_bfloat16* __restrict__ Ch2, __nv_bfloat16* __restrict__ Cl2,
    float scale, int M, int K, int N)
{
    extern __shared__ __align__(16) char dsm[];
    const uint32_t sb = smem_u32(dsm);

    int bx = blockIdx.x;
    if (MODE == 2 && bx >= N / 128) {
        bx -= N / 128;
        Whg = Whg2; Wlg = Wlg2; bias = bias2; Ch = Ch2; Cl = Cl2;
    }
    const int tid  = threadIdx.x;
    const int warp = tid >> 5, lane = tid & 31;
    const int wm   = warp >> 2, wn = warp & 3;
    const int brow = blockIdx.y * 128;
    const int bcol = bx * 128;

    float acc[4][4][4];
#pragma unroll
    for (int mi = 0; mi < 4; mi++)
#pragma unroll
        for (int ni = 0; ni < 4; ni++)
#pragma unroll
            for (int r = 0; r < 4; r++) acc[mi][ni][r] = 0.0f;

    auto issue = [&](int kt, int s) {
        const int k0 = kt * 32;
        const uint32_t st = sb + s * G_STG;
#pragma unroll
        for (int i = 0; i < 2; i++) {
            const int idx = i * 256 + tid;
            const int r = idx >> 2, c = idx & 3;
            const uint32_t d = st + r * 80 + c * 16;
            const size_t go = (size_t)(brow + r) * K + k0 + c * 8;
            cp16(d,         Ahg + go);
            cp16(d + 10240, Alg + go);
        }
#pragma unroll
        for (int i = 0; i < 2; i++) {
            const int idx = i * 256 + tid;
            const int r = idx >> 4, c = idx & 15;
            const uint32_t d = st + 20480 + r * 272 + c * 16;
            const size_t go = (size_t)(k0 + r) * N + bcol + c * 8;
            cp16(d,        Whg + go);
            cp16(d + 8704, Wlg + go);
        }
        cp_commit();
    };

    const int NK = K / 32;
    issue(0, 0);
    issue(1, 1);
    for (int kt = 0; kt < NK; kt++) {
        if (kt + 2 < NK) {
            issue(kt + 2, (kt + 2) & 3);
            asm volatile("cp.async.wait_group 2;" ::: "memory");
        } else if (kt + 1 < NK) {
            asm volatile("cp.async.wait_group 1;" ::: "memory");
        } else {
            asm volatile("cp.async.wait_group 0;" ::: "memory");
        }
        __syncthreads();

        const uint32_t ah = sb + (kt & 3) * G_STG;
        const uint32_t al = ah + 10240;
        const uint32_t bh = ah + 20480;
        const uint32_t bl = ah + 29184;

#pragma unroll
        for (int ks = 0; ks < 2; ks++) {
            uint32_t afh[4][4], afl[4][4], bfh[2][4], bfl[2][4];
#pragma unroll
            for (int mi = 0; mi < 4; mi++) {
                const int row = wm * 64 + mi * 16 + (lane & 15);
                const int col = ks * 16 + (lane >> 4) * 8;
                const uint32_t off = (uint32_t)(row * 40 + col) * 2;
                ldm_x4(afh[mi], ah + off);
                ldm_x4(afl[mi], al + off);
            }
#pragma unroll
            for (int np = 0; np < 2; np++) {
                const int krow = ks * 16 + (lane & 15);
                const int ncol = wn * 32 + np * 16 + ((lane >> 4) & 1) * 8;
                const uint32_t off = (uint32_t)(krow * 136 + ncol) * 2;
                ldm_x4_trans(bfh[np], bh + off);
                ldm_x4_trans(bfl[np], bl + off);
            }
#pragma unroll
            for (int mi = 0; mi < 4; mi++)
#pragma unroll
                for (int ni = 0; ni < 4; ni++) {
                    uint32_t* ph = &bfh[ni >> 1][(ni & 1) * 2];
                    uint32_t* pl = &bfl[ni >> 1][(ni & 1) * 2];
                    mma_bf16(acc[mi][ni], afh[mi], ph);
                    mma_bf16(acc[mi][ni], afh[mi], pl);
                    mma_bf16(acc[mi][ni], afl[mi], ph);
                }
        }
    }

    const int g = lane >> 2, t4 = lane & 3;
#pragma unroll
    for (int mi = 0; mi < 4; mi++) {
        const int row = brow + wm * 64 + mi * 16 + g;
#pragma unroll
        for (int ni = 0; ni < 4; ni++) {
            const int col = bcol + wn * 32 + ni * 8 + 2 * t4;
            const float b0 = bias[col], b1 = bias[col + 1];
            if (MODE == 0) {
                *reinterpret_cast<float2*>(C + (size_t)row * N + col) =
                    make_float2(acc[mi][ni][0] + b0, acc[mi][ni][1] + b1);
                *reinterpret_cast<float2*>(C + (size_t)(row + 8) * N + col) =
                    make_float2(acc[mi][ni][2] + b0, acc[mi][ni][3] + b1);
            } else {
                uint32_t h0, l0, h1, l1;
                split2((acc[mi][ni][0] + b0) * scale, (acc[mi][ni][1] + b1) * scale, h0, l0);
                split2((acc[mi][ni][2] + b0) * scale, (acc[mi][ni][3] + b1) * scale, h1, l1);
                *reinterpret_cast<uint32_t*>(&Ch[(size_t)row * N + col])       = h0;
                *reinterpret_cast<uint32_t*>(&Cl[(size_t)row * N + col])       = l0;
                *reinterpret_cast<uint32_t*>(&Ch[(size_t)(row + 8) * N + col]) = h1;
                *reinterpret_cast<uint32_t*>(&Cl[(size_t)(row + 8) * N + col]) = l1;
            }
        }
    }
}

// ---------------------------------------------------------------------------
// Tensor-core flash attention: QT=64, 128 threads / 4 warps, 2 CTAs/SM.
// 2-stage cp.async K/V pipeline, x4 ldmatrix, split-bf16 output.
// ---------------------------------------------------------------------------
#define A_TS   9216           // one 64x72 bf16 tile (144B rows)
#define A_STG  (4 * A_TS)     // Kh,Kl,Vh,Vl = 36864
#define A_BOFF (2 * A_STG)    // 73728
#define A_DSM  (A_BOFF + 512)

__global__ __launch_bounds__(128, 2) void attn_mma(const float* __restrict__ biasg)
{
    extern __shared__ __align__(16) char dsm[];
    const uint32_t sb = smem_u32(dsm);

    const int tid  = threadIdx.x;
    const int warp = tid >> 5, lane = tid & 31;
    const int g    = lane >> 2, t4 = lane & 3;
    const int q0   = blockIdx.x * 64;
    const int h    = blockIdx.y;
    const int b    = blockIdx.z;

    // ---- Q fragments via stage-0 area ----
    uint32_t qfh[4][4], qfl[4][4];
    {
        const size_t qbase = ((size_t)b * LQ + q0) * D_MODEL + h * D_H;
#pragma unroll
        for (int i = 0; i < 4; i++) {
            const int idx = i * 128 + tid;           // 0..511
            const int r = idx >> 3, c = idx & 7;
            const size_t go = qbase + (size_t)r * D_MODEL + c * 8;
            *reinterpret_cast<uint4*>(dsm + r * 144 + c * 16) =
                *reinterpret_cast<const uint4*>(g_qh + go);
            *reinterpret_cast<uint4*>(dsm + A_TS + r * 144 + c * 16) =
                *reinterpret_cast<const uint4*>(g_ql + go);
        }
        __syncthreads();
        const int rbase = warp * 16;
#pragma unroll
        for (int s = 0; s < 4; s++) {
            const uint32_t off =
                (uint32_t)((rbase + (lane & 15)) * 72 + (lane >> 4) * 8 + s * 16) * 2;
            ldm_x4(qfh[s], sb + off);
            ldm_x4(qfl[s], sb + A_TS + off);
        }
        __syncthreads();
    }

    auto issue = [&](int kt, int s) {
        const size_t kvbase = ((size_t)b * LK + kt * 64) * D_MODEL + h * D_H;
        const uint32_t st = sb + s * A_STG;
#pragma unroll
        for (int i = 0; i < 16; i++) {
            const int tile = i >> 2;
            const int idx = (i & 3) * 128 + tid;     // 0..511
            const int r = idx >> 3, c = idx & 7;
            const size_t go = kvbase + (size_t)r * D_MODEL + c * 8;
            const uint32_t d = st + tile * A_TS + r * 144 + c * 16;
            const __nv_bfloat16* src =
                tile == 0 ? g_kh : tile == 1 ? g_kl : tile == 2 ? g_vh : g_vl;
            cp16(d, src + go);
        }
        if (tid < 16)
            cp16(sb + A_BOFF + s * 256 + tid * 16,
                 biasg + (size_t)b * LK + kt * 64 + tid * 4);
        cp_commit();
    };

    float m0 = -1.0e30f, m1 = -1.0e30f, l0 = 0.0f, l1 = 0.0f;
    float o[8][4];
#pragma unroll
    for (int j = 0; j < 8; j++)
#pragma unroll
        for (int r = 0; r < 4; r++) o[j][r] = 0.0f;

    const int NK = LK / 64;
    issue(0, 0);
    for (int kt = 0; kt < NK; kt++) {
        const int st = kt & 1;
        if (kt + 1 < NK) {
            issue(kt + 1, st ^ 1);
            asm volatile("cp.async.wait_group 1;" ::: "memory");
        } else {
            asm volatile("cp.async.wait_group 0;" ::: "memory");
        }
        __syncthreads();

        const uint32_t khb = sb + st * A_STG;
        const uint32_t klb = khb + A_TS;
        const uint32_t vhb = khb + 2 * A_TS;
        const uint32_t vlb = khb + 3 * A_TS;
        const float* bias_s = reinterpret_cast<const float*>(dsm + A_BOFF + st * 256);

        // ---- S = Q K^T (3-pass split) ----
        float s[8][4];
#pragma unroll
        for (int j = 0; j < 8; j++)
#pragma unroll
            for (int r = 0; r < 4; r++) s[j][r] = 0.0f;

#pragma unroll
        for (int ks = 0; ks < 4; ks++) {
#pragma unroll
            for (int jp = 0; jp < 4; jp++) {
                const int row = jp * 16 + ((lane >> 4) & 1) * 8 + (lane & 7);
                const int col = ks * 16 + ((lane >> 3) & 1) * 8;
                const uint32_t off = (uint32_t)(row * 72 + col) * 2;
                uint32_t kh4[4], kl4[4];
                ldm_x4(kh4, khb + off);
                ldm_x4(kl4, klb + off);
                mma_bf16(s[2 * jp],     qfh[ks], kh4);
                mma_bf16(s[2 * jp],     qfl[ks], kh4);
                mma_bf16(s[2 * jp],     qfh[ks], kl4);
                mma_bf16(s[2 * jp + 1], qfh[ks], kh4 + 2);
                mma_bf16(s[2 * jp + 1], qfl[ks], kh4 + 2);
                mma_bf16(s[2 * jp + 1], qfh[ks], kl4 + 2);
            }
        }

        // ---- mask bias + online softmax ----
        float mx0 = -1.0e30f, mx1 = -1.0e30f;
#pragma unroll
        for (int j = 0; j < 8; j++) {
            const float b0 = bias_s[j * 8 + 2 * t4];
            const float b1 = bias_s[j * 8 + 2 * t4 + 1];
            s[j][0] += b0; s[j][1] += b1;
            s[j][2] += b0; s[j][3] += b1;
            mx0 = fmaxf(mx0, fmaxf(s[j][0], s[j][1]));
            mx1 = fmaxf(mx1, fmaxf(s[j][2], s[j][3]));
        }
        mx0 = fmaxf(mx0, __shfl_xor_sync(0xffffffffu, mx0, 1));
        mx0 = fmaxf(mx0, __shfl_xor_sync(0xffffffffu, mx0, 2));
        mx1 = fmaxf(mx1, __shfl_xor_sync(0xffffffffu, mx1, 1));
        mx1 = fmaxf(mx1, __shfl_xor_sync(0xffffffffu, mx1, 2));

        const float m0n = fmaxf(m0, mx0), m1n = fmaxf(m1, mx1);
        const float c0 = __expf(m0 - m0n), c1 = __expf(m1 - m1n);
        m0 = m0n; m1 = m1n;

        float sum0 = 0.0f, sum1 = 0.0f;
#pragma unroll
        for (int j = 0; j < 8; j++) {
            s[j][0] = __expf(s[j][0] - m0n);
            s[j][1] = __expf(s[j][1] - m0n);
            s[j][2] = __expf(s[j][2] - m1n);
            s[j][3] = __expf(s[j][3] - m1n);
            sum0 += s[j][0] + s[j][1];
            sum1 += s[j][2] + s[j][3];
        }
        sum0 += __shfl_xor_sync(0xffffffffu, sum0, 1);
        sum0 += __shfl_xor_sync(0xffffffffu, sum0, 2);
        sum1 += __shfl_xor_sync(0xffffffffu, sum1, 1);
        sum1 += __shfl_xor_sync(0xffffffffu, sum1, 2);
        l0 = l0 * c0 + sum0;
        l1 = l1 * c1 + sum1;

#pragma unroll
        for (int j = 0; j < 8; j++) {
            o[j][0] *= c0; o[j][1] *= c0;
            o[j][2] *= c1; o[j][3] *= c1;
        }

        // ---- O += P V (3-pass split) ----
#pragma unroll
        for (int ks = 0; ks < 4; ks++) {
            uint32_t pah[4], pal[4];
            split2(s[2 * ks][0],     s[2 * ks][1],     pah[0], pal[0]);
            split2(s[2 * ks][2],     s[2 * ks][3],     pah[1], pal[1]);
            split2(s[2 * ks + 1][0], s[2 * ks + 1][1], pah[2], pal[2]);
            split2(s[2 * ks + 1][2], s[2 * ks + 1][3], pah[3], pal[3]);
#pragma unroll
            for (int jp = 0; jp < 4; jp++) {
                const int row = ks * 16 + (lane & 15);
                const int col = jp * 16 + ((lane >> 4) & 1) * 8;
                const uint32_t off = (uint32_t)(row * 72 + col) * 2;
                uint32_t vh4[4], vl4[4];
                ldm_x4_trans(vh4, vhb + off);
                ldm_x4_trans(vl4, vlb + off);
                mma_bf16(o[2 * jp],     pah, vh4);
                mma_bf16(o[2 * jp],     pal, vh4);
                mma_bf16(o[2 * jp],     pah, vl4);
                mma_bf16(o[2 * jp + 1], pah, vh4 + 2);
                mma_bf16(o[2 * jp + 1], pal, vh4 + 2);
                mma_bf16(o[2 * jp + 1], pah, vl4 + 2);
            }
        }
        __syncthreads();
    }

    // ---- normalize + write split-bf16 output ----
    const float li0 = 1.0f / l0, li1 = 1.0f / l1;
    const int row0 = q0 + warp * 16 + g;
    const size_t base0 = ((size_t)b * LQ + row0) * D_MODEL + h * D_H;
    const size_t base1 = base0 + (size_t)8 * D_MODEL;
#pragma unroll
    for (int j = 0; j < 8; j++) {
        const int col = j * 8 + 2 * t4;
        uint32_t h0, l0r, h1, l1r;
        split2(o[j][0] * li0, o[j][1] * li0, h0, l0r);
        split2(o[j][2] * li1, o[j][3] * li1, h1, l1r);
        *reinterpret_cast<uint32_t*>(&g_ah[base0 + col]) = h0;
        *reinterpret_cast<uint32_t*>(&g_al[base0 + col]) = l0r;
        *reinterpret_cast<uint32_t*>(&g_ah[base1 + col]) = h1;
        *reinterpret_cast<uint32_t*>(&g_al[base1 + col]) = l1r;
    }
}

// ---------------------------------------------------------------------------
// Launch
// ---------------------------------------------------------------------------
extern "C" void kernel_launch(void* const* d_in, const int* in_sizes, int n_in,
                              void* d_out, int out_size)
{
    const float* q_in  = (const float*)d_in[0];
    const float* kv_in = (const float*)d_in[1];
    const int*   mask  = (const int*)  d_in[2];
    const float* W_Q   = (const float*)d_in[3];
    const float* b_Q   = (const float*)d_in[4];
    const float* W_K   = (const float*)d_in[5];
    const float* b_K   = (const float*)d_in[6];
    const float* W_V   = (const float*)d_in[7];
    const float* b_V   = (const float*)d_in[8];
    const float* W_O   = (const float*)d_in[9];
    const float* b_O   = (const float*)d_in[10];

    __nv_bfloat16 *qinh, *qinl, *kvinh, *kvinl;
    __nv_bfloat16 *wqh, *wql, *wkh, *wkl, *wvh, *wvl, *woh, *wol;
    __nv_bfloat16 *qh, *ql, *kh, *kl, *vh, *vl, *ah, *al;
    float* biasf;
    cudaGetSymbolAddress((void**)&qinh,  g_qinh);
    cudaGetSymbolAddress((void**)&qinl,  g_qinl);
    cudaGetSymbolAddress((void**)&kvinh, g_kvinh);
    cudaGetSymbolAddress((void**)&kvinl, g_kvinl);
    cudaGetSymbolAddress((void**)&wqh, g_wqh);  cudaGetSymbolAddress((void**)&wql, g_wql);
    cudaGetSymbolAddress((void**)&wkh, g_wkh);  cudaGetSymbolAddress((void**)&wkl, g_wkl);
    cudaGetSymbolAddress((void**)&wvh, g_wvh);  cudaGetSymbolAddress((void**)&wvl, g_wvl);
    cudaGetSymbolAddress((void**)&woh, g_woh);  cudaGetSymbolAddress((void**)&wol, g_wol);
    cudaGetSymbolAddress((void**)&qh, g_qh);    cudaGetSymbolAddress((void**)&ql, g_ql);
    cudaGetSymbolAddress((void**)&kh, g_kh);    cudaGetSymbolAddress((void**)&kl, g_kl);
    cudaGetSymbolAddress((void**)&vh, g_vh);    cudaGetSymbolAddress((void**)&vl, g_vl);
    cudaGetSymbolAddress((void**)&ah, g_ah);    cudaGetSymbolAddress((void**)&al, g_al);
    cudaGetSymbolAddress((void**)&biasf, g_biasf);

    cudaFuncSetAttribute(gemm_bb<0>, cudaFuncAttributeMaxDynamicSharedMemorySize, GDSM);
    cudaFuncSetAttribute(gemm_bb<1>, cudaFuncAttributeMaxDynamicSharedMemorySize, GDSM);
    cudaFuncSetAttribute(gemm_bb<2>, cudaFuncAttributeMaxDynamicSharedMemorySize, GDSM);
    cudaFuncSetAttribute(attn_mma,   cudaFuncAttributeMaxDynamicSharedMemorySize, A_DSM);

    // ---- pre-split ----
    const int nq4  = BATCH * LQ * D_MODEL / 4;
    const int nkv4 = BATCH * LK * D_MODEL / 4;
    const int nw4  = D_MODEL * D_MODEL / 4;
    split_kernel<<<nq4 / 256, 256>>>(q_in,  qinh,  qinl,  nq4);
    split_kernel<<<nkv4 / 256, 256>>>(kv_in, kvinh, kvinl, nkv4);
    split4_kernel<<<dim3(nw4 / 256, 4), 256>>>(
        W_Q, W_K, W_V, W_O, wqh, wql, wkh, wkl, wvh, wvl, woh, wol, nw4);
    mask_bias_kernel<<<(BATCH * LK) / 256, 256>>>(mask, biasf, BATCH * LK);

    // ---- projections ----
    const dim3 thr(256);
    const dim3 gq(D_MODEL / 128, (BATCH * LQ) / 128);
    const dim3 gkv(2 * D_MODEL / 128, (BATCH * LK) / 128);
    gemm_bb<1><<<gq, thr, GDSM>>>(qinh, qinl, wqh, wql, b_Q, nullptr, qh, ql,
                                  nullptr, nullptr, nullptr, nullptr, nullptr,
                                  0.125f, BATCH * LQ, D_MODEL, D_MODEL);
    gemm_bb<2><<<gkv, thr, GDSM>>>(kvinh, kvinl, wkh, wkl, b_K, nullptr, kh, kl,
                                   wvh, wvl, b_V, vh, vl,
                                   1.0f, BATCH * LK, D_MODEL, D_MODEL);

    // ---- attention ----
    const dim3 ga(LQ / 64, N_HEAD, BATCH);
    attn_mma<<<ga, 128, A_DSM>>>(biasf);

    // ---- output projection ----
    gemm_bb<0><<<gq, thr, GDSM>>>(ah, al, woh, wol, b_O, (float*)d_out,
                                  nullptr, nullptr,
                                  nullptr, nullptr, nullptr, nullptr, nullptr,
                                  1.0f, BATCH * LQ, D_MODEL, D_MODEL);
}

// round 7
// speedup vs baseline: 7.6280x; 1.4104x over previous
#include <cuda_runtime.h>
#include <cuda_bf16.h>
#include <stdint.h>
#include <math.h>

#define D_MODEL 1024
#define N_HEAD  16
#define D_H     64
#define BATCH   4
#define LQ      1024
#define LK      2048

// ---------------------------------------------------------------------------
// Scratch (no cudaMalloc allowed)
// ---------------------------------------------------------------------------
__device__ __nv_bfloat16 g_qinh[(size_t)BATCH * LQ * D_MODEL];
__device__ __nv_bfloat16 g_qinl[(size_t)BATCH * LQ * D_MODEL];
__device__ __nv_bfloat16 g_kvinh[(size_t)BATCH * LK * D_MODEL];
__device__ __nv_bfloat16 g_kvinl[(size_t)BATCH * LK * D_MODEL];
__device__ __nv_bfloat16 g_ckinh[(size_t)BATCH * LK * D_MODEL];  // compacted kv input
__device__ __nv_bfloat16 g_ckinl[(size_t)BATCH * LK * D_MODEL];
__device__ __nv_bfloat16 g_wqh[(size_t)D_MODEL * D_MODEL];
__device__ __nv_bfloat16 g_wql[(size_t)D_MODEL * D_MODEL];
__device__ __nv_bfloat16 g_wkh[(size_t)D_MODEL * D_MODEL];
__device__ __nv_bfloat16 g_wkl[(size_t)D_MODEL * D_MODEL];
__device__ __nv_bfloat16 g_wvh[(size_t)D_MODEL * D_MODEL];
__device__ __nv_bfloat16 g_wvl[(size_t)D_MODEL * D_MODEL];
__device__ __nv_bfloat16 g_woh[(size_t)D_MODEL * D_MODEL];
__device__ __nv_bfloat16 g_wol[(size_t)D_MODEL * D_MODEL];
__device__ __nv_bfloat16 g_qh[(size_t)BATCH * LQ * D_MODEL];
__device__ __nv_bfloat16 g_ql[(size_t)BATCH * LQ * D_MODEL];
__device__ __nv_bfloat16 g_kh[(size_t)BATCH * LK * D_MODEL];
__device__ __nv_bfloat16 g_kl[(size_t)BATCH * LK * D_MODEL];
__device__ __nv_bfloat16 g_vh[(size_t)BATCH * LK * D_MODEL];
__device__ __nv_bfloat16 g_vl[(size_t)BATCH * LK * D_MODEL];
__device__ __nv_bfloat16 g_ah[(size_t)BATCH * LQ * D_MODEL];
__device__ __nv_bfloat16 g_al[(size_t)BATCH * LQ * D_MODEL];
// compaction metadata
__device__ int   g_kidx[(size_t)BATCH * LK];
__device__ int   g_nkv[BATCH];
__device__ int   g_npad[BATCH];
__device__ float g_biasc[(size_t)BATCH * LK];

// ---------------------------------------------------------------------------
// Helpers
// ---------------------------------------------------------------------------
__device__ __forceinline__ uint32_t smem_u32(const void* p) {
    uint32_t a;
    asm("{ .reg .u64 t; cvta.to.shared.u64 t, %1; cvt.u32.u64 %0, t; }"
        : "=r"(a) : "l"(p));
    return a;
}
__device__ __forceinline__ void cp16(uint32_t d, const void* g) {
    asm volatile("cp.async.cg.shared.global [%0], [%1], 16;" :: "r"(d), "l"(g));
}
__device__ __forceinline__ void cp_commit() {
    asm volatile("cp.async.commit_group;" ::: "memory");
}
__device__ __forceinline__ void ldm_x4(uint32_t* r, uint32_t addr) {
    asm volatile("ldmatrix.sync.aligned.m8n8.x4.shared.b16 {%0,%1,%2,%3}, [%4];"
                 : "=r"(r[0]), "=r"(r[1]), "=r"(r[2]), "=r"(r[3]) : "r"(addr));
}
__device__ __forceinline__ void ldm_x4_trans(uint32_t* r, uint32_t addr) {
    asm volatile("ldmatrix.sync.aligned.m8n8.x4.trans.shared.b16 {%0,%1,%2,%3}, [%4];"
                 : "=r"(r[0]), "=r"(r[1]), "=r"(r[2]), "=r"(r[3]) : "r"(addr));
}
__device__ __forceinline__ void mma_bf16(float* c, const uint32_t* a, const uint32_t* b) {
    asm volatile(
        "mma.sync.aligned.m16n8k16.row.col.f32.bf16.bf16.f32 "
        "{%0,%1,%2,%3}, {%4,%5,%6,%7}, {%8,%9}, {%0,%1,%2,%3};"
        : "+f"(c[0]), "+f"(c[1]), "+f"(c[2]), "+f"(c[3])
        : "r"(a[0]), "r"(a[1]), "r"(a[2]), "r"(a[3]), "r"(b[0]), "r"(b[1]));
}
__device__ __forceinline__ void split2(float a, float b, uint32_t& hi, uint32_t& lo) {
    __nv_bfloat162 h2 = __float22bfloat162_rn(make_float2(a, b));
    float2 hf = __bfloat1622float2(h2);
    __nv_bfloat162 l2 = __float22bfloat162_rn(make_float2(a - hf.x, b - hf.y));
    hi = *reinterpret_cast<uint32_t*>(&h2);
    lo = *reinterpret_cast<uint32_t*>(&l2);
}

// ---------------------------------------------------------------------------
// Pre-split kernels
// ---------------------------------------------------------------------------
__global__ __launch_bounds__(256) void split_kernel(
    const float* __restrict__ src, __nv_bfloat16* __restrict__ dh,
    __nv_bfloat16* __restrict__ dl, int n4)
{
    const int i = blockIdx.x * 256 + threadIdx.x;
    if (i < n4) {
        float4 v = reinterpret_cast<const float4*>(src)[i];
        uint32_t h0, l0, h1, l1;
        split2(v.x, v.y, h0, l0);
        split2(v.z, v.w, h1, l1);
        reinterpret_cast<uint2*>(dh)[i] = make_uint2(h0, h1);
        reinterpret_cast<uint2*>(dl)[i] = make_uint2(l0, l1);
    }
}

__global__ __launch_bounds__(256) void split4_kernel(
    const float* __restrict__ s0, const float* __restrict__ s1,
    const float* __restrict__ s2, const float* __restrict__ s3,
    __nv_bfloat16* __restrict__ h0p, __nv_bfloat16* __restrict__ l0p,
    __nv_bfloat16* __restrict__ h1p, __nv_bfloat16* __restrict__ l1p,
    __nv_bfloat16* __restrict__ h2p, __nv_bfloat16* __restrict__ l2p,
    __nv_bfloat16* __restrict__ h3p, __nv_bfloat16* __restrict__ l3p,
    int n4)
{
    const int i = blockIdx.x * 256 + threadIdx.x;
    if (i >= n4) return;
    const float* src; __nv_bfloat16 *dh, *dl;
    switch (blockIdx.y) {
        case 0: src = s0; dh = h0p; dl = l0p; break;
        case 1: src = s1; dh = h1p; dl = l1p; break;
        case 2: src = s2; dh = h2p; dl = l2p; break;
        default: src = s3; dh = h3p; dl = l3p; break;
    }
    float4 v = reinterpret_cast<const float4*>(src)[i];
    uint32_t h0, l0, h1, l1;
    split2(v.x, v.y, h0, l0);
    split2(v.z, v.w, h1, l1);
    reinterpret_cast<uint2*>(dh)[i] = make_uint2(h0, h1);
    reinterpret_cast<uint2*>(dl)[i] = make_uint2(l0, l1);
}

// ---------------------------------------------------------------------------
// Compaction: stable scan of unmasked keys per batch.
// 1 block / batch, 1024 threads, each handles 2 keys.
// ---------------------------------------------------------------------------
__global__ __launch_bounds__(1024) void compact_scan_kernel(const int* __restrict__ mask)
{
    __shared__ int ssum[1024];
    const int b = blockIdx.x, t = threadIdx.x;
    const int* m = mask + (size_t)b * LK;
    const int f0 = (m[2 * t]     == 0) ? 1 : 0;   // keep if NOT masked
    const int f1 = (m[2 * t + 1] == 0) ? 1 : 0;
    ssum[t] = f0 + f1;
    __syncthreads();
    for (int off = 1; off < 1024; off <<= 1) {
        const int v = (t >= off) ? ssum[t - off] : 0;
        __syncthreads();
        ssum[t] += v;
        __syncthreads();
    }
    const int excl = ssum[t] - f0 - f1;
    if (f0) g_kidx[(size_t)b * LK + excl]      = 2 * t;
    if (f1) g_kidx[(size_t)b * LK + excl + f0] = 2 * t + 1;
    const int n = ssum[1023];
    if (t == 0) {
        g_nkv[b]  = n;
        g_npad[b] = (n + 127) & ~127;
    }
    g_biasc[(size_t)b * LK + 2 * t]     = (2 * t     < n) ? 0.0f : -1.0e30f;
    g_biasc[(size_t)b * LK + 2 * t + 1] = (2 * t + 1 < n) ? 0.0f : -1.0e30f;
}

// Gather unmasked kv-input rows into compact buffers (pads zeroed).
// grid (LK/8, BATCH), 256 threads; 8 dst rows per block, 128 uint4 per row.
__global__ __launch_bounds__(256) void gather_kv_kernel()
{
    const int b  = blockIdx.y;
    const int j0 = blockIdx.x * 8;
    const int n = g_nkv[b], npad = g_npad[b];
    if (j0 >= npad) return;
    const int tid = threadIdx.x;
    for (int i = tid; i < 8 * 128; i += 256) {
        const int r = i >> 7, c = i & 127;
        const int j = j0 + r;
        if (j >= npad) continue;
        uint4 vh = make_uint4(0, 0, 0, 0), vl = make_uint4(0, 0, 0, 0);
        if (j < n) {
            const int src = g_kidx[(size_t)b * LK + j];
            const size_t so = ((size_t)b * LK + src) * 128 + c;   // uint4 units
            vh = reinterpret_cast<const uint4*>(g_kvinh)[so];
            vl = reinterpret_cast<const uint4*>(g_kvinl)[so];
        }
        const size_t dof = ((size_t)b * LK + j) * 128 + c;
        reinterpret_cast<uint4*>(g_ckinh)[dof] = vh;
        reinterpret_cast<uint4*>(g_ckinl)[dof] = vl;
    }
}

// ---------------------------------------------------------------------------
// Pipelined bf16-split GEMM (4-stage cp.async, fragment-reuse).
// MODE 0: fp32 out. MODE 1: split-bf16 out. MODE 2: fused K|V on compacted
// input, with per-batch early-exit past npad rows.
// ---------------------------------------------------------------------------
#define G_STG 37888   // Ah 10240 + Al 10240 + Bh 8704 + Bl 8704
#define GDSM  (4 * G_STG)

template <int MODE>
__global__ __launch_bounds__(256) void gemm_bb(
    const __nv_bfloat16* __restrict__ Ahg, const __nv_bfloat16* __restrict__ Alg,
    const __nv_bfloat16* __restrict__ Whg, const __nv_bfloat16* __restrict__ Wlg,
    const float* __restrict__ bias, float* __restrict__ C,
    __nv_bfloat16* __restrict__ Ch, __nv_bfloat16* __restrict__ Cl,
    const __nv_bfloat16* __restrict__ Whg2, const __nv_bfloat16* __restrict__ Wlg2,
    const float* __restrict__ bias2,
    __nv_bfloat16* __restrict__ Ch2, __nv_bfloat16* __restrict__ Cl2,
    float scale, int M, int K, int N)
{
    extern __shared__ __align__(16) char dsm[];
    const uint32_t sb = smem_u32(dsm);

    const int brow = blockIdx.y * 128;
    if (MODE == 2) {
        const int bb = brow / LK;
        if ((brow % LK) >= g_npad[bb]) return;   // compacted: nothing to do
    }
    int bx = blockIdx.x;
    if (MODE == 2 && bx >= N / 128) {
        bx -= N / 128;
        Whg = Whg2; Wlg = Wlg2; bias = bias2; Ch = Ch2; Cl = Cl2;
    }
    const int tid  = threadIdx.x;
    const int warp = tid >> 5, lane = tid & 31;
    const int wm   = warp >> 2, wn = warp & 3;
    const int bcol = bx * 128;

    float acc[4][4][4];
#pragma unroll
    for (int mi = 0; mi < 4; mi++)
#pragma unroll
        for (int ni = 0; ni < 4; ni++)
#pragma unroll
            for (int r = 0; r < 4; r++) acc[mi][ni][r] = 0.0f;

    auto issue = [&](int kt, int s) {
        const int k0 = kt * 32;
        const uint32_t st = sb + s * G_STG;
#pragma unroll
        for (int i = 0; i < 2; i++) {
            const int idx = i * 256 + tid;
            const int r = idx >> 2, c = idx & 3;
            const uint32_t d = st + r * 80 + c * 16;
            const size_t go = (size_t)(brow + r) * K + k0 + c * 8;
            cp16(d,         Ahg + go);
            cp16(d + 10240, Alg + go);
        }
#pragma unroll
        for (int i = 0; i < 2; i++) {
            const int idx = i * 256 + tid;
            const int r = idx >> 4, c = idx & 15;
            const uint32_t d = st + 20480 + r * 272 + c * 16;
            const size_t go = (size_t)(k0 + r) * N + bcol + c * 8;
            cp16(d,        Whg + go);
            cp16(d + 8704, Wlg + go);
        }
        cp_commit();
    };

    const int NK = K / 32;
    issue(0, 0);
    issue(1, 1);
    for (int kt = 0; kt < NK; kt++) {
        if (kt + 2 < NK) {
            issue(kt + 2, (kt + 2) & 3);
            asm volatile("cp.async.wait_group 2;" ::: "memory");
        } else if (kt + 1 < NK) {
            asm volatile("cp.async.wait_group 1;" ::: "memory");
        } else {
            asm volatile("cp.async.wait_group 0;" ::: "memory");
        }
        __syncthreads();

        const uint32_t ah = sb + (kt & 3) * G_STG;
        const uint32_t al = ah + 10240;
        const uint32_t bh = ah + 20480;
        const uint32_t bl = ah + 29184;

#pragma unroll
        for (int ks = 0; ks < 2; ks++) {
            uint32_t afh[4][4], afl[4][4], bfh[2][4], bfl[2][4];
#pragma unroll
            for (int mi = 0; mi < 4; mi++) {
                const int row = wm * 64 + mi * 16 + (lane & 15);
                const int col = ks * 16 + (lane >> 4) * 8;
                const uint32_t off = (uint32_t)(row * 40 + col) * 2;
                ldm_x4(afh[mi], ah + off);
                ldm_x4(afl[mi], al + off);
            }
#pragma unroll
            for (int np = 0; np < 2; np++) {
                const int krow = ks * 16 + (lane & 15);
                const int ncol = wn * 32 + np * 16 + ((lane >> 4) & 1) * 8;
                const uint32_t off = (uint32_t)(krow * 136 + ncol) * 2;
                ldm_x4_trans(bfh[np], bh + off);
                ldm_x4_trans(bfl[np], bl + off);
            }
#pragma unroll
            for (int mi = 0; mi < 4; mi++)
#pragma unroll
                for (int ni = 0; ni < 4; ni++) {
                    uint32_t* ph = &bfh[ni >> 1][(ni & 1) * 2];
                    uint32_t* pl = &bfl[ni >> 1][(ni & 1) * 2];
                    mma_bf16(acc[mi][ni], afh[mi], ph);
                    mma_bf16(acc[mi][ni], afh[mi], pl);
                    mma_bf16(acc[mi][ni], afl[mi], ph);
                }
        }
    }

    const int g = lane >> 2, t4 = lane & 3;
#pragma unroll
    for (int mi = 0; mi < 4; mi++) {
        const int row = brow + wm * 64 + mi * 16 + g;
#pragma unroll
        for (int ni = 0; ni < 4; ni++) {
            const int col = bcol + wn * 32 + ni * 8 + 2 * t4;
            const float b0 = bias[col], b1 = bias[col + 1];
            if (MODE == 0) {
                *reinterpret_cast<float2*>(C + (size_t)row * N + col) =
                    make_float2(acc[mi][ni][0] + b0, acc[mi][ni][1] + b1);
                *reinterpret_cast<float2*>(C + (size_t)(row + 8) * N + col) =
                    make_float2(acc[mi][ni][2] + b0, acc[mi][ni][3] + b1);
            } else {
                uint32_t h0, l0, h1, l1;
                split2((acc[mi][ni][0] + b0) * scale, (acc[mi][ni][1] + b1) * scale, h0, l0);
                split2((acc[mi][ni][2] + b0) * scale, (acc[mi][ni][3] + b1) * scale, h1, l1);
                *reinterpret_cast<uint32_t*>(&Ch[(size_t)row * N + col])       = h0;
                *reinterpret_cast<uint32_t*>(&Cl[(size_t)row * N + col])       = l0;
                *reinterpret_cast<uint32_t*>(&Ch[(size_t)(row + 8) * N + col]) = h1;
                *reinterpret_cast<uint32_t*>(&Cl[(size_t)(row + 8) * N + col]) = l1;
            }
        }
    }
}

// ---------------------------------------------------------------------------
// Tensor-core flash attention over COMPACTED keys (npad[b]/64 tiles).
// QT=64, 128 threads / 4 warps, 2 CTAs/SM, 2-stage cp.async pipeline.
// ---------------------------------------------------------------------------
#define A_TS   9216
#define A_STG  (4 * A_TS)
#define A_BOFF (2 * A_STG)
#define A_DSM  (A_BOFF + 512)

__global__ __launch_bounds__(128, 2) void attn_mma()
{
    extern __shared__ __align__(16) char dsm[];
    const uint32_t sb = smem_u32(dsm);

    const int tid  = threadIdx.x;
    const int warp = tid >> 5, lane = tid & 31;
    const int g    = lane >> 2, t4 = lane & 3;
    const int q0   = blockIdx.x * 64;
    const int h    = blockIdx.y;
    const int b    = blockIdx.z;
    const int NK   = g_npad[b] / 64;

    // ---- Q fragments via stage-0 area ----
    uint32_t qfh[4][4], qfl[4][4];
    {
        const size_t qbase = ((size_t)b * LQ + q0) * D_MODEL + h * D_H;
#pragma unroll
        for (int i = 0; i < 4; i++) {
            const int idx = i * 128 + tid;
            const int r = idx >> 3, c = idx & 7;
            const size_t go = qbase + (size_t)r * D_MODEL + c * 8;
            *reinterpret_cast<uint4*>(dsm + r * 144 + c * 16) =
                *reinterpret_cast<const uint4*>(g_qh + go);
            *reinterpret_cast<uint4*>(dsm + A_TS + r * 144 + c * 16) =
                *reinterpret_cast<const uint4*>(g_ql + go);
        }
        __syncthreads();
        const int rbase = warp * 16;
#pragma unroll
        for (int s = 0; s < 4; s++) {
            const uint32_t off =
                (uint32_t)((rbase + (lane & 15)) * 72 + (lane >> 4) * 8 + s * 16) * 2;
            ldm_x4(qfh[s], sb + off);
            ldm_x4(qfl[s], sb + A_TS + off);
        }
        __syncthreads();
    }

    auto issue = [&](int kt, int s) {
        const size_t kvbase = ((size_t)b * LK + kt * 64) * D_MODEL + h * D_H;
        const uint32_t st = sb + s * A_STG;
#pragma unroll
        for (int i = 0; i < 16; i++) {
            const int tile = i >> 2;
            const int idx = (i & 3) * 128 + tid;
            const int r = idx >> 3, c = idx & 7;
            const size_t go = kvbase + (size_t)r * D_MODEL + c * 8;
            const uint32_t d = st + tile * A_TS + r * 144 + c * 16;
            const __nv_bfloat16* src =
                tile == 0 ? g_kh : tile == 1 ? g_kl : tile == 2 ? g_vh : g_vl;
            cp16(d, src + go);
        }
        if (tid < 16)
            cp16(sb + A_BOFF + s * 256 + tid * 16,
                 g_biasc + (size_t)b * LK + kt * 64 + tid * 4);
        cp_commit();
    };

    float m0 = -1.0e30f, m1 = -1.0e30f, l0 = 0.0f, l1 = 0.0f;
    float o[8][4];
#pragma unroll
    for (int j = 0; j < 8; j++)
#pragma unroll
        for (int r = 0; r < 4; r++) o[j][r] = 0.0f;

    issue(0, 0);
    for (int kt = 0; kt < NK; kt++) {
        const int st = kt & 1;
        if (kt + 1 < NK) {
            issue(kt + 1, st ^ 1);
            asm volatile("cp.async.wait_group 1;" ::: "memory");
        } else {
            asm volatile("cp.async.wait_group 0;" ::: "memory");
        }
        __syncthreads();

        const uint32_t khb = sb + st * A_STG;
        const uint32_t klb = khb + A_TS;
        const uint32_t vhb = khb + 2 * A_TS;
        const uint32_t vlb = khb + 3 * A_TS;
        const float* bias_s = reinterpret_cast<const float*>(dsm + A_BOFF + st * 256);

        // ---- S = Q K^T (3-pass split) ----
        float s[8][4];
#pragma unroll
        for (int j = 0; j < 8; j++)
#pragma unroll
            for (int r = 0; r < 4; r++) s[j][r] = 0.0f;

#pragma unroll
        for (int ks = 0; ks < 4; ks++) {
#pragma unroll
            for (int jp = 0; jp < 4; jp++) {
                const int row = jp * 16 + ((lane >> 4) & 1) * 8 + (lane & 7);
                const int col = ks * 16 + ((lane >> 3) & 1) * 8;
                const uint32_t off = (uint32_t)(row * 72 + col) * 2;
                uint32_t kh4[4], kl4[4];
                ldm_x4(kh4, khb + off);
                ldm_x4(kl4, klb + off);
                mma_bf16(s[2 * jp],     qfh[ks], kh4);
                mma_bf16(s[2 * jp],     qfl[ks], kh4);
                mma_bf16(s[2 * jp],     qfh[ks], kl4);
                mma_bf16(s[2 * jp + 1], qfh[ks], kh4 + 2);
                mma_bf16(s[2 * jp + 1], qfl[ks], kh4 + 2);
                mma_bf16(s[2 * jp + 1], qfh[ks], kl4 + 2);
            }
        }

        // ---- pad bias + online softmax ----
        float mx0 = -1.0e30f, mx1 = -1.0e30f;
#pragma unroll
        for (int j = 0; j < 8; j++) {
            const float b0 = bias_s[j * 8 + 2 * t4];
            const float b1 = bias_s[j * 8 + 2 * t4 + 1];
            s[j][0] += b0; s[j][1] += b1;
            s[j][2] += b0; s[j][3] += b1;
            mx0 = fmaxf(mx0, fmaxf(s[j][0], s[j][1]));
            mx1 = fmaxf(mx1, fmaxf(s[j][2], s[j][3]));
        }
        mx0 = fmaxf(mx0, __shfl_xor_sync(0xffffffffu, mx0, 1));
        mx0 = fmaxf(mx0, __shfl_xor_sync(0xffffffffu, mx0, 2));
        mx1 = fmaxf(mx1, __shfl_xor_sync(0xffffffffu, mx1, 1));
        mx1 = fmaxf(mx1, __shfl_xor_sync(0xffffffffu, mx1, 2));

        const float m0n = fmaxf(m0, mx0), m1n = fmaxf(m1, mx1);
        const float c0 = __expf(m0 - m0n), c1 = __expf(m1 - m1n);
        m0 = m0n; m1 = m1n;

        float sum0 = 0.0f, sum1 = 0.0f;
#pragma unroll
        for (int j = 0; j < 8; j++) {
            s[j][0] = __expf(s[j][0] - m0n);
            s[j][1] = __expf(s[j][1] - m0n);
            s[j][2] = __expf(s[j][2] - m1n);
            s[j][3] = __expf(s[j][3] - m1n);
            sum0 += s[j][0] + s[j][1];
            sum1 += s[j][2] + s[j][3];
        }
        sum0 += __shfl_xor_sync(0xffffffffu, sum0, 1);
        sum0 += __shfl_xor_sync(0xffffffffu, sum0, 2);
        sum1 += __shfl_xor_sync(0xffffffffu, sum1, 1);
        sum1 += __shfl_xor_sync(0xffffffffu, sum1, 2);
        l0 = l0 * c0 + sum0;
        l1 = l1 * c1 + sum1;

#pragma unroll
        for (int j = 0; j < 8; j++) {
            o[j][0] *= c0; o[j][1] *= c0;
            o[j][2] *= c1; o[j][3] *= c1;
        }

        // ---- O += P V (3-pass split) ----
#pragma unroll
        for (int ks = 0; ks < 4; ks++) {
            uint32_t pah[4], pal[4];
            split2(s[2 * ks][0],     s[2 * ks][1],     pah[0], pal[0]);
            split2(s[2 * ks][2],     s[2 * ks][3],     pah[1], pal[1]);
            split2(s[2 * ks + 1][0], s[2 * ks + 1][1], pah[2], pal[2]);
            split2(s[2 * ks + 1][2], s[2 * ks + 1][3], pah[3], pal[3]);
#pragma unroll
            for (int jp = 0; jp < 4; jp++) {
                const int row = ks * 16 + (lane & 15);
                const int col = jp * 16 + ((lane >> 4) & 1) * 8;
                const uint32_t off = (uint32_t)(row * 72 + col) * 2;
                uint32_t vh4[4], vl4[4];
                ldm_x4_trans(vh4, vhb + off);
                ldm_x4_trans(vl4, vlb + off);
                mma_bf16(o[2 * jp],     pah, vh4);
                mma_bf16(o[2 * jp],     pal, vh4);
                mma_bf16(o[2 * jp],     pah, vl4);
                mma_bf16(o[2 * jp + 1], pah, vh4 + 2);
                mma_bf16(o[2 * jp + 1], pal, vh4 + 2);
                mma_bf16(o[2 * jp + 1], pah, vl4 + 2);
            }
        }
        __syncthreads();
    }

    // ---- normalize + write split-bf16 output ----
    const float li0 = 1.0f / l0, li1 = 1.0f / l1;
    const int row0 = q0 + warp * 16 + g;
    const size_t base0 = ((size_t)b * LQ + row0) * D_MODEL + h * D_H;
    const size_t base1 = base0 + (size_t)8 * D_MODEL;
#pragma unroll
    for (int j = 0; j < 8; j++) {
        const int col = j * 8 + 2 * t4;
        uint32_t h0, l0r, h1, l1r;
        split2(o[j][0] * li0, o[j][1] * li0, h0, l0r);
        split2(o[j][2] * li1, o[j][3] * li1, h1, l1r);
        *reinterpret_cast<uint32_t*>(&g_ah[base0 + col]) = h0;
        *reinterpret_cast<uint32_t*>(&g_al[base0 + col]) = l0r;
        *reinterpret_cast<uint32_t*>(&g_ah[base1 + col]) = h1;
        *reinterpret_cast<uint32_t*>(&g_al[base1 + col]) = l1r;
    }
}

// ---------------------------------------------------------------------------
// Launch
// ---------------------------------------------------------------------------
extern "C" void kernel_launch(void* const* d_in, const int* in_sizes, int n_in,
                              void* d_out, int out_size)
{
    const float* q_in  = (const float*)d_in[0];
    const float* kv_in = (const float*)d_in[1];
    const int*   mask  = (const int*)  d_in[2];
    const float* W_Q   = (const float*)d_in[3];
    const float* b_Q   = (const float*)d_in[4];
    const float* W_K   = (const float*)d_in[5];
    const float* b_K   = (const float*)d_in[6];
    const float* W_V   = (const float*)d_in[7];
    const float* b_V   = (const float*)d_in[8];
    const float* W_O   = (const float*)d_in[9];
    const float* b_O   = (const float*)d_in[10];

    __nv_bfloat16 *qinh, *qinl, *kvinh, *kvinl, *ckinh, *ckinl;
    __nv_bfloat16 *wqh, *wql, *wkh, *wkl, *wvh, *wvl, *woh, *wol;
    __nv_bfloat16 *qh, *ql, *kh, *kl, *vh, *vl, *ah, *al;
    cudaGetSymbolAddress((void**)&qinh,  g_qinh);
    cudaGetSymbolAddress((void**)&qinl,  g_qinl);
    cudaGetSymbolAddress((void**)&kvinh, g_kvinh);
    cudaGetSymbolAddress((void**)&kvinl, g_kvinl);
    cudaGetSymbolAddress((void**)&ckinh, g_ckinh);
    cudaGetSymbolAddress((void**)&ckinl, g_ckinl);
    cudaGetSymbolAddress((void**)&wqh, g_wqh);  cudaGetSymbolAddress((void**)&wql, g_wql);
    cudaGetSymbolAddress((void**)&wkh, g_wkh);  cudaGetSymbolAddress((void**)&wkl, g_wkl);
    cudaGetSymbolAddress((void**)&wvh, g_wvh);  cudaGetSymbolAddress((void**)&wvl, g_wvl);
    cudaGetSymbolAddress((void**)&woh, g_woh);  cudaGetSymbolAddress((void**)&wol, g_wol);
    cudaGetSymbolAddress((void**)&qh, g_qh);    cudaGetSymbolAddress((void**)&ql, g_ql);
    cudaGetSymbolAddress((void**)&kh, g_kh);    cudaGetSymbolAddress((void**)&kl, g_kl);
    cudaGetSymbolAddress((void**)&vh, g_vh);    cudaGetSymbolAddress((void**)&vl, g_vl);
    cudaGetSymbolAddress((void**)&ah, g_ah);    cudaGetSymbolAddress((void**)&al, g_al);

    cudaFuncSetAttribute(gemm_bb<0>, cudaFuncAttributeMaxDynamicSharedMemorySize, GDSM);
    cudaFuncSetAttribute(gemm_bb<1>, cudaFuncAttributeMaxDynamicSharedMemorySize, GDSM);
    cudaFuncSetAttribute(gemm_bb<2>, cudaFuncAttributeMaxDynamicSharedMemorySize, GDSM);
    cudaFuncSetAttribute(attn_mma,   cudaFuncAttributeMaxDynamicSharedMemorySize, A_DSM);

    // ---- pre-split + compaction ----
    const int nq4  = BATCH * LQ * D_MODEL / 4;
    const int nkv4 = BATCH * LK * D_MODEL / 4;
    const int nw4  = D_MODEL * D_MODEL / 4;
    split_kernel<<<nq4 / 256, 256>>>(q_in,  qinh,  qinl,  nq4);
    split_kernel<<<nkv4 / 256, 256>>>(kv_in, kvinh, kvinl, nkv4);
    split4_kernel<<<dim3(nw4 / 256, 4), 256>>>(
        W_Q, W_K, W_V, W_O, wqh, wql, wkh, wkl, wvh, wvl, woh, wol, nw4);
    compact_scan_kernel<<<BATCH, 1024>>>(mask);
    gather_kv_kernel<<<dim3(LK / 8, BATCH), 256>>>();

    // ---- projections ----
    const dim3 thr(256);
    const dim3 gq(D_MODEL / 128, (BATCH * LQ) / 128);
    const dim3 gkv(2 * D_MODEL / 128, (BATCH * LK) / 128);
    gemm_bb<1><<<gq, thr, GDSM>>>(qinh, qinl, wqh, wql, b_Q, nullptr, qh, ql,
                                  nullptr, nullptr, nullptr, nullptr, nullptr,
                                  0.125f, BATCH * LQ, D_MODEL, D_MODEL);
    gemm_bb<2><<<gkv, thr, GDSM>>>(ckinh, ckinl, wkh, wkl, b_K, nullptr, kh, kl,
                                   wvh, wvl, b_V, vh, vl,
                                   1.0f, BATCH * LK, D_MODEL, D_MODEL);

    // ---- attention over compacted keys ----
    const dim3 ga(LQ / 64, N_HEAD, BATCH);
    attn_mma<<<ga, 128, A_DSM>>>();

    // ---- output projection ----
    gemm_bb<0><<<gq, thr, GDSM>>>(ah, al, woh, wol, b_O, (float*)d_out,
                                  nullptr, nullptr,
                                  nullptr, nullptr, nullptr, nullptr, nullptr,
                                  1.0f, BATCH * LQ, D_MODEL, D_MODEL);
}

// round 8
// speedup vs baseline: 7.8058x; 1.0233x over previous
#include <cuda_runtime.h>
#include <cuda_bf16.h>
#include <stdint.h>
#include <math.h>

#define D_MODEL 1024
#define N_HEAD  16
#define D_H     64
#define BATCH   4
#define LQ      1024
#define LK      2048

// ---------------------------------------------------------------------------
// Scratch (no cudaMalloc allowed)
// ---------------------------------------------------------------------------
__device__ __nv_bfloat16 g_qinh[(size_t)BATCH * LQ * D_MODEL];
__device__ __nv_bfloat16 g_qinl[(size_t)BATCH * LQ * D_MODEL];
__device__ __nv_bfloat16 g_ckinh[(size_t)BATCH * LK * D_MODEL];  // compacted kv input
__device__ __nv_bfloat16 g_ckinl[(size_t)BATCH * LK * D_MODEL];
__device__ __nv_bfloat16 g_wqh[(size_t)D_MODEL * D_MODEL];
__device__ __nv_bfloat16 g_wql[(size_t)D_MODEL * D_MODEL];
__device__ __nv_bfloat16 g_wkh[(size_t)D_MODEL * D_MODEL];
__device__ __nv_bfloat16 g_wkl[(size_t)D_MODEL * D_MODEL];
__device__ __nv_bfloat16 g_wvh[(size_t)D_MODEL * D_MODEL];
__device__ __nv_bfloat16 g_wvl[(size_t)D_MODEL * D_MODEL];
__device__ __nv_bfloat16 g_woh[(size_t)D_MODEL * D_MODEL];
__device__ __nv_bfloat16 g_wol[(size_t)D_MODEL * D_MODEL];
__device__ __nv_bfloat16 g_qh[(size_t)BATCH * LQ * D_MODEL];
__device__ __nv_bfloat16 g_ql[(size_t)BATCH * LQ * D_MODEL];
__device__ __nv_bfloat16 g_kh[(size_t)BATCH * LK * D_MODEL];
__device__ __nv_bfloat16 g_kl[(size_t)BATCH * LK * D_MODEL];
__device__ __nv_bfloat16 g_vh[(size_t)BATCH * LK * D_MODEL];
__device__ __nv_bfloat16 g_vl[(size_t)BATCH * LK * D_MODEL];
__device__ __nv_bfloat16 g_ah[(size_t)BATCH * LQ * D_MODEL];
__device__ __nv_bfloat16 g_al[(size_t)BATCH * LQ * D_MODEL];
// compaction metadata
__device__ int   g_kidx[(size_t)BATCH * LK];
__device__ int   g_nkv[BATCH];
__device__ int   g_npad[BATCH];
__device__ float g_biasc[(size_t)BATCH * LK];

// ---------------------------------------------------------------------------
// Helpers
// ---------------------------------------------------------------------------
__device__ __forceinline__ uint32_t smem_u32(const void* p) {
    uint32_t a;
    asm("{ .reg .u64 t; cvta.to.shared.u64 t, %1; cvt.u32.u64 %0, t; }"
        : "=r"(a) : "l"(p));
    return a;
}
__device__ __forceinline__ void cp16(uint32_t d, const void* g) {
    asm volatile("cp.async.cg.shared.global [%0], [%1], 16;" :: "r"(d), "l"(g));
}
__device__ __forceinline__ void cp_commit() {
    asm volatile("cp.async.commit_group;" ::: "memory");
}
__device__ __forceinline__ void ldm_x4(uint32_t* r, uint32_t addr) {
    asm volatile("ldmatrix.sync.aligned.m8n8.x4.shared.b16 {%0,%1,%2,%3}, [%4];"
                 : "=r"(r[0]), "=r"(r[1]), "=r"(r[2]), "=r"(r[3]) : "r"(addr));
}
__device__ __forceinline__ void ldm_x4_trans(uint32_t* r, uint32_t addr) {
    asm volatile("ldmatrix.sync.aligned.m8n8.x4.trans.shared.b16 {%0,%1,%2,%3}, [%4];"
                 : "=r"(r[0]), "=r"(r[1]), "=r"(r[2]), "=r"(r[3]) : "r"(addr));
}
__device__ __forceinline__ void mma_bf16(float* c, const uint32_t* a, const uint32_t* b) {
    asm volatile(
        "mma.sync.aligned.m16n8k16.row.col.f32.bf16.bf16.f32 "
        "{%0,%1,%2,%3}, {%4,%5,%6,%7}, {%8,%9}, {%0,%1,%2,%3};"
        : "+f"(c[0]), "+f"(c[1]), "+f"(c[2]), "+f"(c[3])
        : "r"(a[0]), "r"(a[1]), "r"(a[2]), "r"(a[3]), "r"(b[0]), "r"(b[1]));
}
__device__ __forceinline__ void split2(float a, float b, uint32_t& hi, uint32_t& lo) {
    __nv_bfloat162 h2 = __float22bfloat162_rn(make_float2(a, b));
    float2 hf = __bfloat1622float2(h2);
    __nv_bfloat162 l2 = __float22bfloat162_rn(make_float2(a - hf.x, b - hf.y));
    hi = *reinterpret_cast<uint32_t*>(&h2);
    lo = *reinterpret_cast<uint32_t*>(&l2);
}

// ---------------------------------------------------------------------------
// Fused pre-split: q_input + all 4 weights in one launch (range dispatch).
// blocks [0,4096): q_in; [4096,8192): weights (1024 blocks each).
// ---------------------------------------------------------------------------
__global__ __launch_bounds__(256) void split_all_kernel(
    const float* __restrict__ q_in,
    const float* __restrict__ WQ, const float* __restrict__ WK,
    const float* __restrict__ WV, const float* __restrict__ WO)
{
    const int blk = blockIdx.x;
    const float* src;
    __nv_bfloat16 *dh, *dl;
    int base;
    if (blk < 4096) {
        src = q_in; dh = g_qinh; dl = g_qinl; base = blk;
    } else {
        const int w = (blk - 4096) >> 10;
        base = (blk - 4096) & 1023;
        switch (w) {
            case 0:  src = WQ; dh = g_wqh; dl = g_wql; break;
            case 1:  src = WK; dh = g_wkh; dl = g_wkl; break;
            case 2:  src = WV; dh = g_wvh; dl = g_wvl; break;
            default: src = WO; dh = g_woh; dl = g_wol; break;
        }
    }
    const int i = base * 256 + threadIdx.x;
    float4 v = reinterpret_cast<const float4*>(src)[i];
    uint32_t h0, l0, h1, l1;
    split2(v.x, v.y, h0, l0);
    split2(v.z, v.w, h1, l1);
    reinterpret_cast<uint2*>(dh)[i] = make_uint2(h0, h1);
    reinterpret_cast<uint2*>(dl)[i] = make_uint2(l0, l1);
}

// ---------------------------------------------------------------------------
// Compaction scan: 1 block/batch, 1024 threads, 2 keys each.
// ---------------------------------------------------------------------------
__global__ __launch_bounds__(1024) void compact_scan_kernel(const int* __restrict__ mask)
{
    __shared__ int ssum[1024];
    const int b = blockIdx.x, t = threadIdx.x;
    const int* m = mask + (size_t)b * LK;
    const int f0 = (m[2 * t]     == 0) ? 1 : 0;
    const int f1 = (m[2 * t + 1] == 0) ? 1 : 0;
    ssum[t] = f0 + f1;
    __syncthreads();
    for (int off = 1; off < 1024; off <<= 1) {
        const int v = (t >= off) ? ssum[t - off] : 0;
        __syncthreads();
        ssum[t] += v;
        __syncthreads();
    }
    const int excl = ssum[t] - f0 - f1;
    if (f0) g_kidx[(size_t)b * LK + excl]      = 2 * t;
    if (f1) g_kidx[(size_t)b * LK + excl + f0] = 2 * t + 1;
    const int n = ssum[1023];
    if (t == 0) {
        g_nkv[b]  = n;
        g_npad[b] = (n + 127) & ~127;
    }
    g_biasc[(size_t)b * LK + 2 * t]     = (2 * t     < n) ? 0.0f : -1.0e30f;
    g_biasc[(size_t)b * LK + 2 * t + 1] = (2 * t + 1 < n) ? 0.0f : -1.0e30f;
}

// ---------------------------------------------------------------------------
// Fused gather + split: read f32 kv_input rows via kidx, write compact
// split-bf16 (pads zeroed). grid (LK/8, BATCH), 256 threads.
// ---------------------------------------------------------------------------
__global__ __launch_bounds__(256) void gather_split_kernel(const float* __restrict__ kv_in)
{
    const int b  = blockIdx.y;
    const int j0 = blockIdx.x * 8;
    const int n = g_nkv[b], npad = g_npad[b];
    if (j0 >= npad) return;
    const int tid = threadIdx.x;
    for (int i = tid; i < 8 * 256; i += 256) {
        const int r = i >> 8, c = i & 255;          // c: float4 index within row
        const int j = j0 + r;
        if (j >= npad) continue;
        uint2 uh = make_uint2(0, 0), ul = make_uint2(0, 0);
        if (j < n) {
            const int src = g_kidx[(size_t)b * LK + j];
            float4 v = reinterpret_cast<const float4*>(kv_in)
                           [((size_t)b * LK + src) * 256 + c];
            uint32_t h0, l0, h1, l1;
            split2(v.x, v.y, h0, l0);
            split2(v.z, v.w, h1, l1);
            uh = make_uint2(h0, h1);
            ul = make_uint2(l0, l1);
        }
        const size_t dof = ((size_t)b * LK + j) * 256 + c;
        reinterpret_cast<uint2*>(g_ckinh)[dof] = uh;
        reinterpret_cast<uint2*>(g_ckinl)[dof] = ul;
    }
}

// ---------------------------------------------------------------------------
// GEMM core: 128x128 tile, BK=32, 256 thr, 4-stage cp.async, fragment reuse.
// K = N = D_MODEL fixed.
// ---------------------------------------------------------------------------
#define G_STG 37888   // Ah 10240 + Al 10240 + Bh 8704 + Bl 8704
#define GDSM  (4 * G_STG)

__device__ __forceinline__ void gemm_core(
    const __nv_bfloat16* __restrict__ Ahg, const __nv_bfloat16* __restrict__ Alg,
    const __nv_bfloat16* __restrict__ Whg, const __nv_bfloat16* __restrict__ Wlg,
    int brow, int bcol, char* dsm, float acc[4][4][4])
{
    const uint32_t sb = smem_u32(dsm);
    const int tid  = threadIdx.x;
    const int warp = tid >> 5, lane = tid & 31;
    const int wm   = warp >> 2, wn = warp & 3;

#pragma unroll
    for (int mi = 0; mi < 4; mi++)
#pragma unroll
        for (int ni = 0; ni < 4; ni++)
#pragma unroll
            for (int r = 0; r < 4; r++) acc[mi][ni][r] = 0.0f;

    auto issue = [&](int kt, int s) {
        const int k0 = kt * 32;
        const uint32_t st = sb + s * G_STG;
#pragma unroll
        for (int i = 0; i < 2; i++) {
            const int idx = i * 256 + tid;
            const int r = idx >> 2, c = idx & 3;
            const uint32_t d = st + r * 80 + c * 16;
            const size_t go = (size_t)(brow + r) * D_MODEL + k0 + c * 8;
            cp16(d,         Ahg + go);
            cp16(d + 10240, Alg + go);
        }
#pragma unroll
        for (int i = 0; i < 2; i++) {
            const int idx = i * 256 + tid;
            const int r = idx >> 4, c = idx & 15;
            const uint32_t d = st + 20480 + r * 272 + c * 16;
            const size_t go = (size_t)(k0 + r) * D_MODEL + bcol + c * 8;
            cp16(d,        Whg + go);
            cp16(d + 8704, Wlg + go);
        }
        cp_commit();
    };

    const int NK = D_MODEL / 32;
    issue(0, 0);
    issue(1, 1);
    for (int kt = 0; kt < NK; kt++) {
        if (kt + 2 < NK) {
            issue(kt + 2, (kt + 2) & 3);
            asm volatile("cp.async.wait_group 2;" ::: "memory");
        } else if (kt + 1 < NK) {
            asm volatile("cp.async.wait_group 1;" ::: "memory");
        } else {
            asm volatile("cp.async.wait_group 0;" ::: "memory");
        }
        __syncthreads();

        const uint32_t ah = sb + (kt & 3) * G_STG;
        const uint32_t al = ah + 10240;
        const uint32_t bh = ah + 20480;
        const uint32_t bl = ah + 29184;

#pragma unroll
        for (int ks = 0; ks < 2; ks++) {
            uint32_t afh[4][4], afl[4][4], bfh[2][4], bfl[2][4];
#pragma unroll
            for (int mi = 0; mi < 4; mi++) {
                const int row = wm * 64 + mi * 16 + (lane & 15);
                const int col = ks * 16 + (lane >> 4) * 8;
                const uint32_t off = (uint32_t)(row * 40 + col) * 2;
                ldm_x4(afh[mi], ah + off);
                ldm_x4(afl[mi], al + off);
            }
#pragma unroll
            for (int np = 0; np < 2; np++) {
                const int krow = ks * 16 + (lane & 15);
                const int ncol = wn * 32 + np * 16 + ((lane >> 4) & 1) * 8;
                const uint32_t off = (uint32_t)(krow * 136 + ncol) * 2;
                ldm_x4_trans(bfh[np], bh + off);
                ldm_x4_trans(bfl[np], bl + off);
            }
#pragma unroll
            for (int mi = 0; mi < 4; mi++)
#pragma unroll
                for (int ni = 0; ni < 4; ni++) {
                    uint32_t* ph = &bfh[ni >> 1][(ni & 1) * 2];
                    uint32_t* pl = &bfl[ni >> 1][(ni & 1) * 2];
                    mma_bf16(acc[mi][ni], afh[mi], ph);
                    mma_bf16(acc[mi][ni], afh[mi], pl);
                    mma_bf16(acc[mi][ni], afl[mi], ph);
                }
        }
    }
}

// ---------------------------------------------------------------------------
// Fused Q + K + V projection GEMM. grid (16, 96):
//   y <  32: Q rows (bx<8 valid), out g_qh/g_ql scaled by 0.125
//   y >= 32: compacted KV rows (early-exit past npad); bx<8 -> K else V
// ---------------------------------------------------------------------------
__global__ __launch_bounds__(256) void gemm_qkv(
    const float* __restrict__ bQ, const float* __restrict__ bK,
    const float* __restrict__ bV)
{
    extern __shared__ __align__(16) char dsm[];

    const __nv_bfloat16 *Ahg, *Alg, *Whg, *Wlg;
    const float* bias;
    __nv_bfloat16 *Ch, *Cl;
    float scale;
    int brow, bx = blockIdx.x;

    if (blockIdx.y < 32) {
        if (bx >= 8) return;
        Ahg = g_qinh; Alg = g_qinl; Whg = g_wqh; Wlg = g_wql;
        bias = bQ; Ch = g_qh; Cl = g_ql; scale = 0.125f;
        brow = blockIdx.y * 128;
    } else {
        brow = (blockIdx.y - 32) * 128;
        const int bb = brow / LK;
        if ((brow % LK) >= g_npad[bb]) return;
        Ahg = g_ckinh; Alg = g_ckinl; scale = 1.0f;
        if (bx < 8) { Whg = g_wkh; Wlg = g_wkl; bias = bK; Ch = g_kh; Cl = g_kl; }
        else { bx -= 8; Whg = g_wvh; Wlg = g_wvl; bias = bV; Ch = g_vh; Cl = g_vl; }
    }
    const int bcol = bx * 128;

    float acc[4][4][4];
    gemm_core(Ahg, Alg, Whg, Wlg, brow, bcol, dsm, acc);

    const int lane = threadIdx.x & 31, warp = threadIdx.x >> 5;
    const int wm = warp >> 2, wn = warp & 3;
    const int g = lane >> 2, t4 = lane & 3;
#pragma unroll
    for (int mi = 0; mi < 4; mi++) {
        const int row = brow + wm * 64 + mi * 16 + g;
#pragma unroll
        for (int ni = 0; ni < 4; ni++) {
            const int col = bcol + wn * 32 + ni * 8 + 2 * t4;
            const float b0 = bias[col], b1 = bias[col + 1];
            uint32_t h0, l0, h1, l1;
            split2((acc[mi][ni][0] + b0) * scale, (acc[mi][ni][1] + b1) * scale, h0, l0);
            split2((acc[mi][ni][2] + b0) * scale, (acc[mi][ni][3] + b1) * scale, h1, l1);
            *reinterpret_cast<uint32_t*>(&Ch[(size_t)row * D_MODEL + col])       = h0;
            *reinterpret_cast<uint32_t*>(&Cl[(size_t)row * D_MODEL + col])       = l0;
            *reinterpret_cast<uint32_t*>(&Ch[(size_t)(row + 8) * D_MODEL + col]) = h1;
            *reinterpret_cast<uint32_t*>(&Cl[(size_t)(row + 8) * D_MODEL + col]) = l1;
        }
    }
}

// Output projection: fp32 out to d_out.
__global__ __launch_bounds__(256) void gemm_o(
    const float* __restrict__ bO, float* __restrict__ C)
{
    extern __shared__ __align__(16) char dsm[];
    const int brow = blockIdx.y * 128;
    const int bcol = blockIdx.x * 128;

    float acc[4][4][4];
    gemm_core(g_ah, g_al, g_woh, g_wol, brow, bcol, dsm, acc);

    const int lane = threadIdx.x & 31, warp = threadIdx.x >> 5;
    const int wm = warp >> 2, wn = warp & 3;
    const int g = lane >> 2, t4 = lane & 3;
#pragma unroll
    for (int mi = 0; mi < 4; mi++) {
        const int row = brow + wm * 64 + mi * 16 + g;
#pragma unroll
        for (int ni = 0; ni < 4; ni++) {
            const int col = bcol + wn * 32 + ni * 8 + 2 * t4;
            const float b0 = bO[col], b1 = bO[col + 1];
            *reinterpret_cast<float2*>(C + (size_t)row * D_MODEL + col) =
                make_float2(acc[mi][ni][0] + b0, acc[mi][ni][1] + b1);
            *reinterpret_cast<float2*>(C + (size_t)(row + 8) * D_MODEL + col) =
                make_float2(acc[mi][ni][2] + b0, acc[mi][ni][3] + b1);
        }
    }
}

// ---------------------------------------------------------------------------
// Tensor-core flash attention over compacted keys (npad[b]/64 tiles).
// QT=64, 128 threads / 4 warps, 2 CTAs/SM, 2-stage cp.async pipeline.
// ---------------------------------------------------------------------------
#define A_TS   9216
#define A_STG  (4 * A_TS)
#define A_BOFF (2 * A_STG)
#define A_DSM  (A_BOFF + 512)

__global__ __launch_bounds__(128, 2) void attn_mma()
{
    extern __shared__ __align__(16) char dsm[];
    const uint32_t sb = smem_u32(dsm);

    const int tid  = threadIdx.x;
    const int warp = tid >> 5, lane = tid & 31;
    const int g    = lane >> 2, t4 = lane & 3;
    const int q0   = blockIdx.x * 64;
    const int h    = blockIdx.y;
    const int b    = blockIdx.z;
    const int NK   = g_npad[b] / 64;

    // ---- Q fragments via stage-0 area ----
    uint32_t qfh[4][4], qfl[4][4];
    {
        const size_t qbase = ((size_t)b * LQ + q0) * D_MODEL + h * D_H;
#pragma unroll
        for (int i = 0; i < 4; i++) {
            const int idx = i * 128 + tid;
            const int r = idx >> 3, c = idx & 7;
            const size_t go = qbase + (size_t)r * D_MODEL + c * 8;
            *reinterpret_cast<uint4*>(dsm + r * 144 + c * 16) =
                *reinterpret_cast<const uint4*>(g_qh + go);
            *reinterpret_cast<uint4*>(dsm + A_TS + r * 144 + c * 16) =
                *reinterpret_cast<const uint4*>(g_ql + go);
        }
        __syncthreads();
        const int rbase = warp * 16;
#pragma unroll
        for (int s = 0; s < 4; s++) {
            const uint32_t off =
                (uint32_t)((rbase + (lane & 15)) * 72 + (lane >> 4) * 8 + s * 16) * 2;
            ldm_x4(qfh[s], sb + off);
            ldm_x4(qfl[s], sb + A_TS + off);
        }
        __syncthreads();
    }

    auto issue = [&](int kt, int s) {
        const size_t kvbase = ((size_t)b * LK + kt * 64) * D_MODEL + h * D_H;
        const uint32_t st = sb + s * A_STG;
#pragma unroll
        for (int i = 0; i < 16; i++) {
            const int tile = i >> 2;
            const int idx = (i & 3) * 128 + tid;
            const int r = idx >> 3, c = idx & 7;
            const size_t go = kvbase + (size_t)r * D_MODEL + c * 8;
            const uint32_t d = st + tile * A_TS + r * 144 + c * 16;
            const __nv_bfloat16* src =
                tile == 0 ? g_kh : tile == 1 ? g_kl : tile == 2 ? g_vh : g_vl;
            cp16(d, src + go);
        }
        if (tid < 16)
            cp16(sb + A_BOFF + s * 256 + tid * 16,
                 g_biasc + (size_t)b * LK + kt * 64 + tid * 4);
        cp_commit();
    };

    float m0 = -1.0e30f, m1 = -1.0e30f, l0 = 0.0f, l1 = 0.0f;
    float o[8][4];
#pragma unroll
    for (int j = 0; j < 8; j++)
#pragma unroll
        for (int r = 0; r < 4; r++) o[j][r] = 0.0f;

    issue(0, 0);
    for (int kt = 0; kt < NK; kt++) {
        const int st = kt & 1;
        if (kt + 1 < NK) {
            issue(kt + 1, st ^ 1);
            asm volatile("cp.async.wait_group 1;" ::: "memory");
        } else {
            asm volatile("cp.async.wait_group 0;" ::: "memory");
        }
        __syncthreads();

        const uint32_t khb = sb + st * A_STG;
        const uint32_t klb = khb + A_TS;
        const uint32_t vhb = khb + 2 * A_TS;
        const uint32_t vlb = khb + 3 * A_TS;
        const float* bias_s = reinterpret_cast<const float*>(dsm + A_BOFF + st * 256);

        // ---- S = Q K^T (3-pass split) ----
        float s[8][4];
#pragma unroll
        for (int j = 0; j < 8; j++)
#pragma unroll
            for (int r = 0; r < 4; r++) s[j][r] = 0.0f;

#pragma unroll
        for (int ks = 0; ks < 4; ks++) {
#pragma unroll
            for (int jp = 0; jp < 4; jp++) {
                const int row = jp * 16 + ((lane >> 4) & 1) * 8 + (lane & 7);
                const int col = ks * 16 + ((lane >> 3) & 1) * 8;
                const uint32_t off = (uint32_t)(row * 72 + col) * 2;
                uint32_t kh4[4], kl4[4];
                ldm_x4(kh4, khb + off);
                ldm_x4(kl4, klb + off);
                mma_bf16(s[2 * jp],     qfh[ks], kh4);
                mma_bf16(s[2 * jp],     qfl[ks], kh4);
                mma_bf16(s[2 * jp],     qfh[ks], kl4);
                mma_bf16(s[2 * jp + 1], qfh[ks], kh4 + 2);
                mma_bf16(s[2 * jp + 1], qfl[ks], kh4 + 2);
                mma_bf16(s[2 * jp + 1], qfh[ks], kl4 + 2);
            }
        }

        // ---- pad bias + online softmax ----
        float mx0 = -1.0e30f, mx1 = -1.0e30f;
#pragma unroll
        for (int j = 0; j < 8; j++) {
            const float b0 = bias_s[j * 8 + 2 * t4];
            const float b1 = bias_s[j * 8 + 2 * t4 + 1];
            s[j][0] += b0; s[j][1] += b1;
            s[j][2] += b0; s[j][3] += b1;
            mx0 = fmaxf(mx0, fmaxf(s[j][0], s[j][1]));
            mx1 = fmaxf(mx1, fmaxf(s[j][2], s[j][3]));
        }
        mx0 = fmaxf(mx0, __shfl_xor_sync(0xffffffffu, mx0, 1));
        mx0 = fmaxf(mx0, __shfl_xor_sync(0xffffffffu, mx0, 2));
        mx1 = fmaxf(mx1, __shfl_xor_sync(0xffffffffu, mx1, 1));
        mx1 = fmaxf(mx1, __shfl_xor_sync(0xffffffffu, mx1, 2));

        const float m0n = fmaxf(m0, mx0), m1n = fmaxf(m1, mx1);
        const float c0 = __expf(m0 - m0n), c1 = __expf(m1 - m1n);
        m0 = m0n; m1 = m1n;

        float sum0 = 0.0f, sum1 = 0.0f;
#pragma unroll
        for (int j = 0; j < 8; j++) {
            s[j][0] = __expf(s[j][0] - m0n);
            s[j][1] = __expf(s[j][1] - m0n);
            s[j][2] = __expf(s[j][2] - m1n);
            s[j][3] = __expf(s[j][3] - m1n);
            sum0 += s[j][0] + s[j][1];
            sum1 += s[j][2] + s[j][3];
        }
        sum0 += __shfl_xor_sync(0xffffffffu, sum0, 1);
        sum0 += __shfl_xor_sync(0xffffffffu, sum0, 2);
        sum1 += __shfl_xor_sync(0xffffffffu, sum1, 1);
        sum1 += __shfl_xor_sync(0xffffffffu, sum1, 2);
        l0 = l0 * c0 + sum0;
        l1 = l1 * c1 + sum1;

#pragma unroll
        for (int j = 0; j < 8; j++) {
            o[j][0] *= c0; o[j][1] *= c0;
            o[j][2] *= c1; o[j][3] *= c1;
        }

        // ---- O += P V (3-pass split) ----
#pragma unroll
        for (int ks = 0; ks < 4; ks++) {
            uint32_t pah[4], pal[4];
            split2(s[2 * ks][0],     s[2 * ks][1],     pah[0], pal[0]);
            split2(s[2 * ks][2],     s[2 * ks][3],     pah[1], pal[1]);
            split2(s[2 * ks + 1][0], s[2 * ks + 1][1], pah[2], pal[2]);
            split2(s[2 * ks + 1][2], s[2 * ks + 1][3], pah[3], pal[3]);
#pragma unroll
            for (int jp = 0; jp < 4; jp++) {
                const int row = ks * 16 + (lane & 15);
                const int col = jp * 16 + ((lane >> 4) & 1) * 8;
                const uint32_t off = (uint32_t)(row * 72 + col) * 2;
                uint32_t vh4[4], vl4[4];
                ldm_x4_trans(vh4, vhb + off);
                ldm_x4_trans(vl4, vlb + off);
                mma_bf16(o[2 * jp],     pah, vh4);
                mma_bf16(o[2 * jp],     pal, vh4);
                mma_bf16(o[2 * jp],     pah, vl4);
                mma_bf16(o[2 * jp + 1], pah, vh4 + 2);
                mma_bf16(o[2 * jp + 1], pal, vh4 + 2);
                mma_bf16(o[2 * jp + 1], pah, vl4 + 2);
            }
        }
        __syncthreads();
    }

    // ---- normalize + write split-bf16 output ----
    const float li0 = 1.0f / l0, li1 = 1.0f / l1;
    const int row0 = q0 + warp * 16 + g;
    const size_t base0 = ((size_t)b * LQ + row0) * D_MODEL + h * D_H;
    const size_t base1 = base0 + (size_t)8 * D_MODEL;
#pragma unroll
    for (int j = 0; j < 8; j++) {
        const int col = j * 8 + 2 * t4;
        uint32_t h0, l0r, h1, l1r;
        split2(o[j][0] * li0, o[j][1] * li0, h0, l0r);
        split2(o[j][2] * li1, o[j][3] * li1, h1, l1r);
        *reinterpret_cast<uint32_t*>(&g_ah[base0 + col]) = h0;
        *reinterpret_cast<uint32_t*>(&g_al[base0 + col]) = l0r;
        *reinterpret_cast<uint32_t*>(&g_ah[base1 + col]) = h1;
        *reinterpret_cast<uint32_t*>(&g_al[base1 + col]) = l1r;
    }
}

// ---------------------------------------------------------------------------
// Launch
// ---------------------------------------------------------------------------
extern "C" void kernel_launch(void* const* d_in, const int* in_sizes, int n_in,
                              void* d_out, int out_size)
{
    const float* q_in  = (const float*)d_in[0];
    const float* kv_in = (const float*)d_in[1];
    const int*   mask  = (const int*)  d_in[2];
    const float* W_Q   = (const float*)d_in[3];
    const float* b_Q   = (const float*)d_in[4];
    const float* W_K   = (const float*)d_in[5];
    const float* b_K   = (const float*)d_in[6];
    const float* W_V   = (const float*)d_in[7];
    const float* b_V   = (const float*)d_in[8];
    const float* W_O   = (const float*)d_in[9];
    const float* b_O   = (const float*)d_in[10];

    cudaFuncSetAttribute(gemm_qkv, cudaFuncAttributeMaxDynamicSharedMemorySize, GDSM);
    cudaFuncSetAttribute(gemm_o,   cudaFuncAttributeMaxDynamicSharedMemorySize, GDSM);
    cudaFuncSetAttribute(attn_mma, cudaFuncAttributeMaxDynamicSharedMemorySize, A_DSM);

    // ---- preprocessing: splits + compaction ----
    split_all_kernel<<<8192, 256>>>(q_in, W_Q, W_K, W_V, W_O);
    compact_scan_kernel<<<BATCH, 1024>>>(mask);
    gather_split_kernel<<<dim3(LK / 8, BATCH), 256>>>(kv_in);

    // ---- fused Q/K/V projections ----
    gemm_qkv<<<dim3(16, 96), 256, GDSM>>>(b_Q, b_K, b_V);

    // ---- attention over compacted keys ----
    attn_mma<<<dim3(LQ / 64, N_HEAD, BATCH), 128, A_DSM>>>();

    // ---- output projection ----
    gemm_o<<<dim3(8, 32), 256, GDSM>>>(b_O, (float*)d_out);
}